// round 13
// baseline (speedup 1.0000x reference)
#include <cuda_runtime.h>
#include <cuda_bf16.h>
#include <math.h>

typedef unsigned int u32;

// ---------------------------------------------------------------------------
// Problem constants
// ---------------------------------------------------------------------------
#define CUTOFF     5.0f
#define A_PATH     0.20412414523193150818f   // 1/sqrt(24)
#define INV_SQRT3  0.57735026918962576451f
#define INV_SQRT8  0.35355339059327376220f
#define PI_OVER_C  0.62831853071795864769f   // pi / 5

#define NNMAX 50000
__device__ float g_xnorm[NNMAX * 40];
__device__ float g_agg[NNMAX * 41];                      // agg0 | agg1 | norm
__device__ __align__(16) unsigned short g_w2bf[36864];   // W2^T bf16, [j][h] row-major

__device__ __forceinline__ float sigf(float x) {
    return __fdividef(1.0f, 1.0f + __expf(-x));
}

// m16n8k16 bf16 MMA, fp32 accumulate (baseline PTX, works on plain sm_103)
__device__ __forceinline__ void mma_bf16(float& d0, float& d1, float& d2, float& d3,
                                         u32 a0, u32 a1, u32 a2, u32 a3,
                                         u32 b0, u32 b1)
{
    asm volatile(
        "mma.sync.aligned.m16n8k16.row.col.f32.bf16.bf16.f32 "
        "{%0,%1,%2,%3}, {%4,%5,%6,%7}, {%8,%9}, {%0,%1,%2,%3};"
        : "+f"(d0), "+f"(d1), "+f"(d2), "+f"(d3)
        : "r"(a0), "r"(a1), "r"(a2), "r"(a3), "r"(b0), "r"(b1));
}

// ---------------------------------------------------------------------------
// Kernel P: W2 -> bf16 transposed  g_w2bf[j*64+h] = bf16(wr2[h*576+j])
// ---------------------------------------------------------------------------
__global__ void k_prep(const float* __restrict__ wr2)
{
    int idx = blockIdx.x * blockDim.x + threadIdx.x;
    if (idx >= 36864) return;
    int j = idx >> 6, h = idx & 63;
    g_w2bf[idx] = __bfloat16_as_ushort(__float2bfloat16_rn(wr2[h * 576 + j]));
}

// ---------------------------------------------------------------------------
// Kernel 0: zero aggregation scratch
// ---------------------------------------------------------------------------
__global__ void k_zero(int total)
{
    int i = blockIdx.x * blockDim.x + threadIdx.x;
    int nf4 = total >> 2;
    float4 z = make_float4(0.f, 0.f, 0.f, 0.f);
    if (i < nf4) ((float4*)g_agg)[i] = z;
    if (i < (total & 3)) g_agg[(nf4 << 2) + i] = 0.f;
}

// ---------------------------------------------------------------------------
// Kernel 1: irrep norm
// ---------------------------------------------------------------------------
__global__ void __launch_bounds__(256)
k_norm(const float* __restrict__ x, int nN)
{
    __shared__ float sx[256 * 40];
    int base = blockIdx.x * 256;
    int nNodes = nN - base; if (nNodes > 256) nNodes = 256;
    int nf4 = nNodes * 10;

    const float4* xin = (const float4*)(x + (size_t)base * 40);
    for (int i = threadIdx.x; i < nf4; i += 256) ((float4*)sx)[i] = xin[i];
    __syncthreads();

    int t = threadIdx.x;
    if (t < nNodes) {
        float* b = sx + t * 40;
        float ss = 0.f, vs = 0.f;
#pragma unroll
        for (int i = 0; i < 16; i++) ss = fmaf(b[i], b[i], ss);
#pragma unroll
        for (int i = 16; i < 40; i++) vs = fmaf(b[i], b[i], vs);
        float inv_s = rsqrtf(ss * 0.0625f + 1e-8f);
        float inv_v = rsqrtf(vs * 0.125f  + 1e-8f);
#pragma unroll
        for (int i = 0; i < 16; i++) b[i] *= inv_s;
#pragma unroll
        for (int i = 16; i < 40; i++) b[i] *= inv_v;
    }
    __syncthreads();
    float4* xout = (float4*)(g_xnorm + (size_t)base * 40);
    for (int i = threadIdx.x; i < nf4; i += 256) xout[i] = ((float4*)sx)[i];
}

// ---------------------------------------------------------------------------
// Kernel 2: HMMA edge kernel. CTA = 256 edges, 8 warps.
//   Both 16-row tiles of each warp processed TOGETHER: B fragments loaded
//   once and fed to two independent MMA chains (4 chains live in m0 loop).
// ---------------------------------------------------------------------------
__global__ void __launch_bounds__(256)
k_edge_mma(const int*   __restrict__ esrc,  const int*   __restrict__ edst,
           const float* __restrict__ esh,   const float* __restrict__ erbf,
           const float* __restrict__ elen,
           const float* __restrict__ wr1,   const float* __restrict__ br1,
           const float* __restrict__ br2g,
           const float* __restrict__ wg1,   const float* __restrict__ bg1,
           const float* __restrict__ wg2,   const float* __restrict__ bg2,
           int E, int nN)
{
    extern __shared__ __align__(16) u32 dynsm[];
    u32*   sB32  = dynsm;                     // 20736
    u32*   sA32  = dynsm + 20736;             // 9216
    float* sCoef = (float*)(dynsm + 29952);   // 17408
    float* sBr2  = sCoef + 17408;             // 576
    float* sWr1  = sBr2 + 576;                // 512
    float* sWg1  = sWr1 + 512;                // 512
    float* sWg2  = sWg1 + 512;                // 64
    float* sBr1  = sWg2 + 64;                 // 64
    float* sBg1  = sBr1 + 64;                 // 64
    int*   sDst  = (int*)(sBg1 + 64);         // 256

    const int tid  = threadIdx.x;
    const int lane = tid & 31;
    const int wid  = tid >> 5;
    const int g    = lane >> 2;
    const int tig  = lane & 3;

    // ---- stage B (bf16 W2^T) into padded rows
    {
        const uint4* src = (const uint4*)g_w2bf;
        for (int i = tid; i < 4608; i += 256) {
            int j = i >> 3, q = i & 7;
            *(uint4*)(sB32 + j * 36 + q * 4) = src[i];
        }
    }
    for (int i = tid; i < 512; i += 256) { sWr1[i] = wr1[i]; sWg1[i] = wg1[i]; }
    for (int i = tid; i < 64;  i += 256) { sWg2[i] = wg2[i]; sBr1[i] = br1[i]; sBg1[i] = bg1[i]; }
    for (int i = tid; i < 576; i += 256) sBr2[i] = br2g[i];

    // ---- per-edge scalar stage
    int e = blockIdx.x * 256 + tid;
    bool valid = e < E;
    int ec = valid ? e : (E - 1);
    int src_n = esrc[ec];
    int dst_n = edst[ec];
    float4 sh4 = ((const float4*)esh)[ec];
    const float sh0 = sh4.x, s1x = sh4.y, s1y = sh4.z, s1z = sh4.w;
    float len = elen[ec];

    float rb[8];
    {
        const float4* rp = (const float4*)(erbf + (size_t)ec * 8);
        float4 r0 = rp[0], r1 = rp[1];
        rb[0] = r0.x; rb[1] = r0.y; rb[2] = r0.z; rb[3] = r0.w;
        rb[4] = r1.x; rb[5] = r1.y; rb[6] = r1.z; rb[7] = r1.w;
    }

    __syncthreads();   // weights staged before use

    float H[64], G[64];
#pragma unroll
    for (int h = 0; h < 64; h++) { H[h] = sBr1[h]; G[h] = sBg1[h]; }
#pragma unroll 1
    for (int r = 0; r < 8; r++) {
        float rv = rb[r];
        const float4* wrp = (const float4*)(sWr1 + r * 64);
        const float4* wgp = (const float4*)(sWg1 + r * 64);
#pragma unroll
        for (int h4 = 0; h4 < 16; h4++) {
            float4 wa = wrp[h4], wb = wgp[h4];
            H[4*h4+0] = fmaf(rv, wa.x, H[4*h4+0]);
            H[4*h4+1] = fmaf(rv, wa.y, H[4*h4+1]);
            H[4*h4+2] = fmaf(rv, wa.z, H[4*h4+2]);
            H[4*h4+3] = fmaf(rv, wa.w, H[4*h4+3]);
            G[4*h4+0] = fmaf(rv, wb.x, G[4*h4+0]);
            G[4*h4+1] = fmaf(rv, wb.y, G[4*h4+1]);
            G[4*h4+2] = fmaf(rv, wb.z, G[4*h4+2]);
            G[4*h4+3] = fmaf(rv, wb.w, G[4*h4+3]);
        }
    }
    float z = 0.f;
#pragma unroll
    for (int h = 0; h < 64; h++) {
        float hr = H[h]; H[h] = hr * sigf(hr);   // silu
        float hg = G[h]; z = fmaf(hg * sigf(hg), sWg2[h], z);
    }
    float gw = sigf(z + bg2[0]);
    float cw = (len < CUTOFF) ? 0.5f * (cosf(PI_OVER_C * len) + 1.0f) : 0.0f;
    float ew = (valid ? cw * gw : 0.0f);

    // ---- write A row (bf16 pairs)
    {
        u32* arow = sA32 + tid * 36;
#pragma unroll
        for (int q = 0; q < 8; q++) {
            int h = q * 8;
            u32 w0 = (u32)__bfloat16_as_ushort(__float2bfloat16_rn(H[h+0]))
                   | ((u32)__bfloat16_as_ushort(__float2bfloat16_rn(H[h+1])) << 16);
            u32 w1 = (u32)__bfloat16_as_ushort(__float2bfloat16_rn(H[h+2]))
                   | ((u32)__bfloat16_as_ushort(__float2bfloat16_rn(H[h+3])) << 16);
            u32 w2 = (u32)__bfloat16_as_ushort(__float2bfloat16_rn(H[h+4]))
                   | ((u32)__bfloat16_as_ushort(__float2bfloat16_rn(H[h+5])) << 16);
            u32 w3 = (u32)__bfloat16_as_ushort(__float2bfloat16_rn(H[h+6]))
                   | ((u32)__bfloat16_as_ushort(__float2bfloat16_rn(H[h+7])) << 16);
            *(uint4*)(arow + q * 4) = make_uint4(w0, w1, w2, w3);
        }
    }

    // ---- write per-edge coefficients (SoA, conflict-free columns)
    {
        float xe[40];
        const float4* xr = (const float4*)(g_xnorm + (size_t)src_n * 40);
#pragma unroll
        for (int q = 0; q < 10; q++) ((float4*)xe)[q] = xr[q];

#pragma unroll
        for (int i = 0; i < 16; i++) sCoef[i * 256 + tid] = xe[i] * sh0;             // cA 0..15
#pragma unroll
        for (int i = 0; i < 8; i++)                                                   // cA 16..23
            sCoef[(16 + i) * 256 + tid] =
                INV_SQRT3 * (xe[16 + 3*i] * s1x + xe[17 + 3*i] * s1y + xe[18 + 3*i] * s1z);
#pragma unroll
        for (int i = 0; i < 16; i++) sCoef[(24 + i) * 256 + tid] = xe[i];             // xs
#pragma unroll
        for (int i = 0; i < 8; i++) {                                                 // pv
            sCoef[(40 + 3*i + 0) * 256 + tid] = xe[16 + 3*i] * sh0;
            sCoef[(40 + 3*i + 1) * 256 + tid] = xe[17 + 3*i] * sh0;
            sCoef[(40 + 3*i + 2) * 256 + tid] = xe[18 + 3*i] * sh0;
        }
        sCoef[64 * 256 + tid] = s1x;
        sCoef[65 * 256 + tid] = s1y;
        sCoef[66 * 256 + tid] = s1z;
        sCoef[67 * 256 + tid] = ew;
        sDst[tid] = valid ? dst_n : 0;
    }
    __syncthreads();

    // ---- warp GEMM + fragment epilogue (both 16-row tiles together)
    float* agg1 = g_agg + (size_t)nN * 16;
    float* nrmp = g_agg + (size_t)nN * 40;

    const int ea0 = wid * 32 + g;        // rt0 rows
    const int ea1 = ea0 + 8;
    const int eb0 = ea0 + 16;            // rt1 rows
    const int eb1 = ea0 + 24;

    // A fragments for both row tiles
    u32 afr0[16], afr1[16];
    {
        const u32* a00 = sA32 + (size_t)ea0 * 36;
        const u32* a01 = sA32 + (size_t)ea1 * 36;
        const u32* a10 = sA32 + (size_t)eb0 * 36;
        const u32* a11 = sA32 + (size_t)eb1 * 36;
#pragma unroll
        for (int ks = 0; ks < 4; ks++) {
            afr0[ks*4+0] = a00[tig + ks*8];
            afr0[ks*4+1] = a01[tig + ks*8];
            afr0[ks*4+2] = a00[tig + 4 + ks*8];
            afr0[ks*4+3] = a01[tig + 4 + ks*8];
            afr1[ks*4+0] = a10[tig + ks*8];
            afr1[ks*4+1] = a11[tig + ks*8];
            afr1[ks*4+2] = a10[tig + 4 + ks*8];
            afr1[ks*4+3] = a11[tig + 4 + ks*8];
        }
    }

    // accumulators: [rt][edge-in-tile] ...
    float Am0a[4] = {0,0,0,0}, Am0b[4] = {0,0,0,0};   // rt0
    float Bm0a[4] = {0,0,0,0}, Bm0b[4] = {0,0,0,0};   // rt1
    float uA0 = 0.f, uA1 = 0.f, uA2 = 0.f, uA3 = 0.f; // rt0: (e0 c0,c1)(e1 c0,c1)
    float uB0 = 0.f, uB1 = 0.f, uB2 = 0.f, uB3 = 0.f; // rt1
    float Am1a[6] = {0,0,0,0,0,0}, Am1b[6] = {0,0,0,0,0,0};
    float Bm1a[6] = {0,0,0,0,0,0}, Bm1b[6] = {0,0,0,0,0,0};

    // ===== m0 region: cols 0..383 (i = 0..23, tiles ct = 2i, 2i+1) =====
#pragma unroll 1
    for (int i = 0; i < 24; i++) {
        float cf00 = sCoef[i * 256 + ea0];
        float cf01 = sCoef[i * 256 + ea1];
        float cf10 = sCoef[i * 256 + eb0];
        float cf11 = sCoef[i * 256 + eb1];
#pragma unroll
        for (int t = 0; t < 2; t++) {
            const u32* br = sB32 + (size_t)((2*i + t) * 8 + g) * 36;
            u32 bb[8];
#pragma unroll
            for (int ks = 0; ks < 4; ks++) { bb[2*ks] = br[tig + ks*8]; bb[2*ks+1] = br[tig + 4 + ks*8]; }
            float d00=0.f,d01=0.f,d02=0.f,d03=0.f;
            float d10=0.f,d11=0.f,d12=0.f,d13=0.f;
#pragma unroll
            for (int ks = 0; ks < 4; ks++) {
                mma_bf16(d00,d01,d02,d03, afr0[ks*4],afr0[ks*4+1],afr0[ks*4+2],afr0[ks*4+3], bb[2*ks],bb[2*ks+1]);
                mma_bf16(d10,d11,d12,d13, afr1[ks*4],afr1[ks*4+1],afr1[ks*4+2],afr1[ks*4+3], bb[2*ks],bb[2*ks+1]);
            }
            int J0 = i * 16 + t * 8 + 2 * tig;
            float2 bias = *(const float2*)(sBr2 + J0);
            int s = t * 2;
            Am0a[s+0] = fmaf(cf00, d00 + bias.x, Am0a[s+0]);
            Am0a[s+1] = fmaf(cf00, d01 + bias.y, Am0a[s+1]);
            Am0b[s+0] = fmaf(cf01, d02 + bias.x, Am0b[s+0]);
            Am0b[s+1] = fmaf(cf01, d03 + bias.y, Am0b[s+1]);
            Bm0a[s+0] = fmaf(cf10, d10 + bias.x, Bm0a[s+0]);
            Bm0a[s+1] = fmaf(cf10, d11 + bias.y, Bm0a[s+1]);
            Bm0b[s+0] = fmaf(cf11, d12 + bias.x, Bm0b[s+0]);
            Bm0b[s+1] = fmaf(cf11, d13 + bias.y, Bm0b[s+1]);
        }
    }

    // ===== w3 region: cols 384..511 (i = 0..15, ct = 48+i) =====
#pragma unroll 1
    for (int i = 0; i < 16; i++) {
        float xs00 = sCoef[(24 + i) * 256 + ea0];
        float xs01 = sCoef[(24 + i) * 256 + ea1];
        float xs10 = sCoef[(24 + i) * 256 + eb0];
        float xs11 = sCoef[(24 + i) * 256 + eb1];
        const u32* br = sB32 + (size_t)((48 + i) * 8 + g) * 36;
        u32 bb[8];
#pragma unroll
        for (int ks = 0; ks < 4; ks++) { bb[2*ks] = br[tig + ks*8]; bb[2*ks+1] = br[tig + 4 + ks*8]; }
        float d00=0.f,d01=0.f,d02=0.f,d03=0.f;
        float d10=0.f,d11=0.f,d12=0.f,d13=0.f;
#pragma unroll
        for (int ks = 0; ks < 4; ks++) {
            mma_bf16(d00,d01,d02,d03, afr0[ks*4],afr0[ks*4+1],afr0[ks*4+2],afr0[ks*4+3], bb[2*ks],bb[2*ks+1]);
            mma_bf16(d10,d11,d12,d13, afr1[ks*4],afr1[ks*4+1],afr1[ks*4+2],afr1[ks*4+3], bb[2*ks],bb[2*ks+1]);
        }
        int J0 = 384 + i * 8 + 2 * tig;
        float2 bias = *(const float2*)(sBr2 + J0);
        uA0 = fmaf(xs00, d00 + bias.x, uA0);
        uA1 = fmaf(xs00, d01 + bias.y, uA1);
        uA2 = fmaf(xs01, d02 + bias.x, uA2);
        uA3 = fmaf(xs01, d03 + bias.y, uA3);
        uB0 = fmaf(xs10, d10 + bias.x, uB0);
        uB1 = fmaf(xs10, d11 + bias.y, uB1);
        uB2 = fmaf(xs11, d12 + bias.x, uB2);
        uB3 = fmaf(xs11, d13 + bias.y, uB3);
    }

    // ===== w4 region: cols 512..575 (i = 0..7, ct = 64+i) =====
#pragma unroll 1
    for (int i = 0; i < 8; i++) {
        const u32* br = sB32 + (size_t)((64 + i) * 8 + g) * 36;
        u32 bb[8];
#pragma unroll
        for (int ks = 0; ks < 4; ks++) { bb[2*ks] = br[tig + ks*8]; bb[2*ks+1] = br[tig + 4 + ks*8]; }
        float d00=0.f,d01=0.f,d02=0.f,d03=0.f;
        float d10=0.f,d11=0.f,d12=0.f,d13=0.f;
#pragma unroll
        for (int ks = 0; ks < 4; ks++) {
            mma_bf16(d00,d01,d02,d03, afr0[ks*4],afr0[ks*4+1],afr0[ks*4+2],afr0[ks*4+3], bb[2*ks],bb[2*ks+1]);
            mma_bf16(d10,d11,d12,d13, afr1[ks*4],afr1[ks*4+1],afr1[ks*4+2],afr1[ks*4+3], bb[2*ks],bb[2*ks+1]);
        }
        int J0 = 512 + i * 8 + 2 * tig;
        float2 bias = *(const float2*)(sBr2 + J0);
        {   // rt0
            float p0x = sCoef[(40 + 3*i + 0) * 256 + ea0];
            float p0y = sCoef[(40 + 3*i + 1) * 256 + ea0];
            float p0z = sCoef[(40 + 3*i + 2) * 256 + ea0];
            float p1x = sCoef[(40 + 3*i + 0) * 256 + ea1];
            float p1y = sCoef[(40 + 3*i + 1) * 256 + ea1];
            float p1z = sCoef[(40 + 3*i + 2) * 256 + ea1];
            float t0 = d00 + bias.x, t1 = d01 + bias.y;
            float t2 = d02 + bias.x, t3 = d03 + bias.y;
            Am1a[0] = fmaf(p0x, t0, Am1a[0]);
            Am1a[1] = fmaf(p0y, t0, Am1a[1]);
            Am1a[2] = fmaf(p0z, t0, Am1a[2]);
            Am1a[3] = fmaf(p0x, t1, Am1a[3]);
            Am1a[4] = fmaf(p0y, t1, Am1a[4]);
            Am1a[5] = fmaf(p0z, t1, Am1a[5]);
            Am1b[0] = fmaf(p1x, t2, Am1b[0]);
            Am1b[1] = fmaf(p1y, t2, Am1b[1]);
            Am1b[2] = fmaf(p1z, t2, Am1b[2]);
            Am1b[3] = fmaf(p1x, t3, Am1b[3]);
            Am1b[4] = fmaf(p1y, t3, Am1b[4]);
            Am1b[5] = fmaf(p1z, t3, Am1b[5]);
        }
        {   // rt1
            float p0x = sCoef[(40 + 3*i + 0) * 256 + eb0];
            float p0y = sCoef[(40 + 3*i + 1) * 256 + eb0];
            float p0z = sCoef[(40 + 3*i + 2) * 256 + eb0];
            float p1x = sCoef[(40 + 3*i + 0) * 256 + eb1];
            float p1y = sCoef[(40 + 3*i + 1) * 256 + eb1];
            float p1z = sCoef[(40 + 3*i + 2) * 256 + eb1];
            float t0 = d10 + bias.x, t1 = d11 + bias.y;
            float t2 = d12 + bias.x, t3 = d13 + bias.y;
            Bm1a[0] = fmaf(p0x, t0, Bm1a[0]);
            Bm1a[1] = fmaf(p0y, t0, Bm1a[1]);
            Bm1a[2] = fmaf(p0z, t0, Bm1a[2]);
            Bm1a[3] = fmaf(p0x, t1, Bm1a[3]);
            Bm1a[4] = fmaf(p0y, t1, Bm1a[4]);
            Bm1a[5] = fmaf(p0z, t1, Bm1a[5]);
            Bm1b[0] = fmaf(p1x, t2, Bm1b[0]);
            Bm1b[1] = fmaf(p1y, t2, Bm1b[1]);
            Bm1b[2] = fmaf(p1z, t2, Bm1b[2]);
            Bm1b[3] = fmaf(p1x, t3, Bm1b[3]);
            Bm1b[4] = fmaf(p1y, t3, Bm1b[4]);
            Bm1b[5] = fmaf(p1z, t3, Bm1b[5]);
        }
    }

    // fold U (w3 path) into m1 with each edge's sh1
    {
        float sx, sy, sz;
        sx = sCoef[64*256 + ea0]; sy = sCoef[65*256 + ea0]; sz = sCoef[66*256 + ea0];
        Am1a[0] = fmaf(uA0, sx, Am1a[0]); Am1a[1] = fmaf(uA0, sy, Am1a[1]); Am1a[2] = fmaf(uA0, sz, Am1a[2]);
        Am1a[3] = fmaf(uA1, sx, Am1a[3]); Am1a[4] = fmaf(uA1, sy, Am1a[4]); Am1a[5] = fmaf(uA1, sz, Am1a[5]);
        sx = sCoef[64*256 + ea1]; sy = sCoef[65*256 + ea1]; sz = sCoef[66*256 + ea1];
        Am1b[0] = fmaf(uA2, sx, Am1b[0]); Am1b[1] = fmaf(uA2, sy, Am1b[1]); Am1b[2] = fmaf(uA2, sz, Am1b[2]);
        Am1b[3] = fmaf(uA3, sx, Am1b[3]); Am1b[4] = fmaf(uA3, sy, Am1b[4]); Am1b[5] = fmaf(uA3, sz, Am1b[5]);
        sx = sCoef[64*256 + eb0]; sy = sCoef[65*256 + eb0]; sz = sCoef[66*256 + eb0];
        Bm1a[0] = fmaf(uB0, sx, Bm1a[0]); Bm1a[1] = fmaf(uB0, sy, Bm1a[1]); Bm1a[2] = fmaf(uB0, sz, Bm1a[2]);
        Bm1a[3] = fmaf(uB1, sx, Bm1a[3]); Bm1a[4] = fmaf(uB1, sy, Bm1a[4]); Bm1a[5] = fmaf(uB1, sz, Bm1a[5]);
        sx = sCoef[64*256 + eb1]; sy = sCoef[65*256 + eb1]; sz = sCoef[66*256 + eb1];
        Bm1b[0] = fmaf(uB2, sx, Bm1b[0]); Bm1b[1] = fmaf(uB2, sy, Bm1b[1]); Bm1b[2] = fmaf(uB2, sz, Bm1b[2]);
        Bm1b[3] = fmaf(uB3, sx, Bm1b[3]); Bm1b[4] = fmaf(uB3, sy, Bm1b[4]); Bm1b[5] = fmaf(uB3, sz, Bm1b[5]);
    }

    // ---- scatter (lane-local slots), both row tiles
    {
        int j0 = 2 * tig;
        // rt0
        {
            float ew0 = sCoef[67 * 256 + ea0];
            float ew1 = sCoef[67 * 256 + ea1];
            int   dA  = sDst[ea0];
            int   dB  = sDst[ea1];
            float ca = A_PATH * ew0;
            float cb = A_PATH * ew1;

            float* base0 = g_agg + (size_t)dA * 16;
            atomicAdd(base0 + j0,     ca * Am0a[0]);
            atomicAdd(base0 + j0 + 1, ca * Am0a[1]);
            atomicAdd(base0 + j0 + 8, ca * Am0a[2]);
            atomicAdd(base0 + j0 + 9, ca * Am0a[3]);
            float* base1 = g_agg + (size_t)dB * 16;
            atomicAdd(base1 + j0,     cb * Am0b[0]);
            atomicAdd(base1 + j0 + 1, cb * Am0b[1]);
            atomicAdd(base1 + j0 + 8, cb * Am0b[2]);
            atomicAdd(base1 + j0 + 9, cb * Am0b[3]);

            float* v0 = agg1 + (size_t)dA * 24;
            float* v1 = agg1 + (size_t)dB * 24;
#pragma unroll
            for (int c = 0; c < 3; c++) {
                atomicAdd(v0 + 3*j0 + c,     ca * Am1a[c]);
                atomicAdd(v0 + 3*(j0+1) + c, ca * Am1a[3+c]);
                atomicAdd(v1 + 3*j0 + c,     cb * Am1b[c]);
                atomicAdd(v1 + 3*(j0+1) + c, cb * Am1b[3+c]);
            }
            if (tig == 0) {
                atomicAdd(nrmp + dA, ew0);
                atomicAdd(nrmp + dB, ew1);
            }
        }
        // rt1
        {
            float ew0 = sCoef[67 * 256 + eb0];
            float ew1 = sCoef[67 * 256 + eb1];
            int   dA  = sDst[eb0];
            int   dB  = sDst[eb1];
            float ca = A_PATH * ew0;
            float cb = A_PATH * ew1;

            float* base0 = g_agg + (size_t)dA * 16;
            atomicAdd(base0 + j0,     ca * Bm0a[0]);
            atomicAdd(base0 + j0 + 1, ca * Bm0a[1]);
            atomicAdd(base0 + j0 + 8, ca * Bm0a[2]);
            atomicAdd(base0 + j0 + 9, ca * Bm0a[3]);
            float* base1 = g_agg + (size_t)dB * 16;
            atomicAdd(base1 + j0,     cb * Bm0b[0]);
            atomicAdd(base1 + j0 + 1, cb * Bm0b[1]);
            atomicAdd(base1 + j0 + 8, cb * Bm0b[2]);
            atomicAdd(base1 + j0 + 9, cb * Bm0b[3]);

            float* v0 = agg1 + (size_t)dA * 24;
            float* v1 = agg1 + (size_t)dB * 24;
#pragma unroll
            for (int c = 0; c < 3; c++) {
                atomicAdd(v0 + 3*j0 + c,     ca * Bm1a[c]);
                atomicAdd(v0 + 3*(j0+1) + c, ca * Bm1a[3+c]);
                atomicAdd(v1 + 3*j0 + c,     cb * Bm1b[c]);
                atomicAdd(v1 + 3*(j0+1) + c, cb * Bm1b[3+c]);
            }
            if (tig == 0) {
                atomicAdd(nrmp + dA, ew0);
                atomicAdd(nrmp + dB, ew1);
            }
        }
    }
}

// ---------------------------------------------------------------------------
// Kernel 3: node update (gates + small matmuls + residual)
// ---------------------------------------------------------------------------
__global__ void __launch_bounds__(256)
k_node(const float* __restrict__ x,
       const float* __restrict__ Wms, const float* __restrict__ Wmv,
       const float* __restrict__ Wus, const float* __restrict__ Wuv,
       const float* __restrict__ Wss, const float* __restrict__ Wsv,
       const float* __restrict__ rsp,
       float* __restrict__ out, int nN)
{
    __shared__ float sWms[384], sWmv[64], sWus[256], sWuv[64], sWss[256], sWsv[64];
    int t = threadIdx.x;
    for (int i = t; i < 384; i += blockDim.x) sWms[i] = Wms[i];
    for (int i = t; i < 256; i += blockDim.x) { sWus[i] = Wus[i]; sWss[i] = Wss[i]; }
    for (int i = t; i < 64;  i += blockDim.x) { sWmv[i] = Wmv[i]; sWuv[i] = Wuv[i]; sWsv[i] = Wsv[i]; }
    __syncthreads();

    int n = blockIdx.x * blockDim.x + t;
    if (n >= nN) return;

    float rs = rsp[0];
    float nrm = fmaxf(g_agg[(size_t)nN * 40 + n], 1e-8f);
    float inv = __fdividef(1.0f, nrm);

    float a0[16], a1[24];
    {
        const float4* p0 = (const float4*)(g_agg + (size_t)n * 16);
#pragma unroll
        for (int q = 0; q < 4; q++) ((float4*)a0)[q] = p0[q];
        const float4* p1 = (const float4*)(g_agg + (size_t)nN * 16 + (size_t)n * 24);
#pragma unroll
        for (int q = 0; q < 6; q++) ((float4*)a1)[q] = p1[q];
    }
#pragma unroll
    for (int j = 0; j < 16; j++) a0[j] *= inv;
#pragma unroll
    for (int j = 0; j < 24; j++) a1[j] *= inv;

    float sc[24];
#pragma unroll
    for (int j = 0; j < 24; j++) sc[j] = 0.f;
#pragma unroll
    for (int i = 0; i < 16; i++) {
        float ai = a0[i];
#pragma unroll
        for (int j = 0; j < 24; j++) sc[j] = fmaf(ai, sWms[i * 24 + j], sc[j]);
    }

    float scal[16], gate[8];
#pragma unroll
    for (int j = 0; j < 16; j++) { float v = 0.25f * sc[j]; scal[j] = v * sigf(v); }
#pragma unroll
    for (int j = 0; j < 8;  j++) gate[j] = sigf(0.25f * sc[16 + j]);

    float vg[24];
#pragma unroll
    for (int j = 0; j < 8; j++) {
#pragma unroll
        for (int c = 0; c < 3; c++) {
            float acc = 0.f;
#pragma unroll
            for (int i = 0; i < 8; i++) acc = fmaf(a1[i * 3 + c], sWmv[i * 8 + j], acc);
            vg[3 * j + c] = acc * INV_SQRT8 * gate[j];
        }
    }

    float xs[16], xv[24];
    {
        const float4* xn = (const float4*)(g_xnorm + (size_t)n * 40);
#pragma unroll
        for (int q = 0; q < 4; q++) ((float4*)xs)[q] = xn[q];
#pragma unroll
        for (int q = 0; q < 6; q++) ((float4*)xv)[q] = xn[4 + q];
    }

    float xi[40];
    {
        const float4* xp = (const float4*)(x + (size_t)n * 40);
#pragma unroll
        for (int q = 0; q < 10; q++) ((float4*)xi)[q] = xp[q];
    }

    float ob[40];
#pragma unroll
    for (int j = 0; j < 16; j++) {
        float acc = 0.f;
#pragma unroll
        for (int i = 0; i < 16; i++) {
            acc = fmaf(scal[i], sWus[i * 16 + j], acc);
            acc = fmaf(xs[i],   sWss[i * 16 + j], acc);
        }
        ob[j] = xi[j] + rs * 0.25f * acc;
    }
#pragma unroll
    for (int j = 0; j < 8; j++) {
#pragma unroll
        for (int c = 0; c < 3; c++) {
            float acc = 0.f;
#pragma unroll
            for (int i = 0; i < 8; i++) {
                acc = fmaf(vg[3 * i + c], sWuv[i * 8 + j], acc);
                acc = fmaf(xv[3 * i + c], sWsv[i * 8 + j], acc);
            }
            ob[16 + 3 * j + c] = xi[16 + 3 * j + c] + rs * INV_SQRT8 * acc;
        }
    }

    float4* o = (float4*)(out + (size_t)n * 40);
#pragma unroll
    for (int q = 0; q < 10; q++) o[q] = ((float4*)ob)[q];
}

// ---------------------------------------------------------------------------
// Launch
// ---------------------------------------------------------------------------
extern "C" void kernel_launch(void* const* d_in, const int* in_sizes, int n_in,
                              void* d_out, int out_size)
{
    const float* x    = (const float*)d_in[0];
    const int*   esrc = (const int*)  d_in[1];
    const int*   edst = (const int*)  d_in[2];
    const float* esh  = (const float*)d_in[3];
    const float* erbf = (const float*)d_in[4];
    const float* elen = (const float*)d_in[5];
    const float* wr1  = (const float*)d_in[6];
    const float* br1  = (const float*)d_in[7];
    const float* wr2  = (const float*)d_in[8];
    const float* br2  = (const float*)d_in[9];
    const float* wg1  = (const float*)d_in[10];
    const float* bg1  = (const float*)d_in[11];
    const float* wg2  = (const float*)d_in[12];
    const float* bg2  = (const float*)d_in[13];
    const float* Wms  = (const float*)d_in[14];
    const float* Wmv  = (const float*)d_in[15];
    const float* Wus  = (const float*)d_in[16];
    const float* Wuv  = (const float*)d_in[17];
    const float* Wss  = (const float*)d_in[18];
    const float* Wsv  = (const float*)d_in[19];
    const float* rsp  = (const float*)d_in[20];

    int nN = in_sizes[0] / 40;
    int E  = in_sizes[1];
    float* out = (float*)d_out;

    size_t shbytes = 49408u * 4u;   // 197632 B
    cudaFuncSetAttribute(k_edge_mma, cudaFuncAttributeMaxDynamicSharedMemorySize, (int)shbytes);

    k_prep<<<(36864 + 255) / 256, 256>>>(wr2);
    int totalz = nN * 41;
    k_zero<<<(totalz / 4 + 255) / 256, 256>>>(totalz);
    k_norm<<<(nN + 255) / 256, 256>>>(x, nN);
    k_edge_mma<<<(E + 255) / 256, 256, shbytes>>>(esrc, edst, esh, erbf, elen,
                                                  wr1, br1, br2,
                                                  wg1, bg1, wg2, bg2, E, nN);
    k_node<<<(nN + 255) / 256, 256>>>(x, Wms, Wmv, Wus, Wuv, Wss, Wsv, rsp, out, nN);
}

// round 15
// speedup vs baseline: 1.6557x; 1.6557x over previous
#include <cuda_runtime.h>
#include <cuda_bf16.h>
#include <math.h>

typedef unsigned int u32;

// ---------------------------------------------------------------------------
// Problem constants
// ---------------------------------------------------------------------------
#define CUTOFF     5.0f
#define A_PATH     0.20412414523193150818f   // 1/sqrt(24)
#define INV_SQRT3  0.57735026918962576451f
#define INV_SQRT8  0.35355339059327376220f
#define PI_OVER_C  0.62831853071795864769f   // pi / 5

#define NNMAX 50000
__device__ float g_xnorm[NNMAX * 40];
__device__ float g_agg[NNMAX * 41];                      // agg0 | agg1 | norm
__device__ __align__(16) unsigned short g_w2bf[36864];   // W2^T bf16, [j][h] row-major

// smem layout (u32 offsets)
#define OFF_B    0        // 20736 : W2^T bf16 rows of 36 u32
#define OFF_A    20736    // 18432 : A tile, 512 rows of 36 u32
#define OFF_CF   39168    // 12288 : bf16[48][512]  xs(0..15) xv(16..39) bcoef(40..47)
#define OFF_SH   51456    //  2048 : fp32[4][512]   sh0 s1x s1y s1z
#define OFF_EW   53504    //   512 : fp32 ew
#define OFF_DST  54016    //   512 : int dst
#define OFF_BR2  54528    //   576
#define OFF_WR1  55104    //   512
#define OFF_WG1  55616    //   512
#define OFF_WG2  56128    //    64
#define OFF_BR1  56192    //    64
#define OFF_BG1  56256    //    64
#define SMEM_U32 56320    // 225280 bytes

__device__ __forceinline__ float sigf(float x) {
    return __fdividef(1.0f, 1.0f + __expf(-x));
}

// m16n8k16 bf16 MMA, fp32 accumulate (baseline PTX, works on plain sm_103)
__device__ __forceinline__ void mma_bf16(float& d0, float& d1, float& d2, float& d3,
                                         u32 a0, u32 a1, u32 a2, u32 a3,
                                         u32 b0, u32 b1)
{
    asm volatile(
        "mma.sync.aligned.m16n8k16.row.col.f32.bf16.bf16.f32 "
        "{%0,%1,%2,%3}, {%4,%5,%6,%7}, {%8,%9}, {%0,%1,%2,%3};"
        : "+f"(d0), "+f"(d1), "+f"(d2), "+f"(d3)
        : "r"(a0), "r"(a1), "r"(a2), "r"(a3), "r"(b0), "r"(b1));
}

__device__ __forceinline__ u32 pack_bf2(float a, float b) {
    return (u32)__bfloat16_as_ushort(__float2bfloat16_rn(a))
         | ((u32)__bfloat16_as_ushort(__float2bfloat16_rn(b)) << 16);
}
__device__ __forceinline__ float bf2f(__nv_bfloat16 v) { return __bfloat162float(v); }

// ---------------------------------------------------------------------------
// Kernel P: W2 -> bf16 transposed  g_w2bf[j*64+h] = bf16(wr2[h*576+j])
// ---------------------------------------------------------------------------
__global__ void k_prep(const float* __restrict__ wr2)
{
    int idx = blockIdx.x * blockDim.x + threadIdx.x;
    if (idx >= 36864) return;
    int j = idx >> 6, h = idx & 63;
    g_w2bf[idx] = __bfloat16_as_ushort(__float2bfloat16_rn(wr2[h * 576 + j]));
}

// ---------------------------------------------------------------------------
// Kernel 0: zero aggregation scratch
// ---------------------------------------------------------------------------
__global__ void k_zero(int total)
{
    int i = blockIdx.x * blockDim.x + threadIdx.x;
    int nf4 = total >> 2;
    float4 z = make_float4(0.f, 0.f, 0.f, 0.f);
    if (i < nf4) ((float4*)g_agg)[i] = z;
    if (i < (total & 3)) g_agg[(nf4 << 2) + i] = 0.f;
}

// ---------------------------------------------------------------------------
// Kernel 1: irrep norm
// ---------------------------------------------------------------------------
__global__ void __launch_bounds__(256)
k_norm(const float* __restrict__ x, int nN)
{
    __shared__ float sx[256 * 40];
    int base = blockIdx.x * 256;
    int nNodes = nN - base; if (nNodes > 256) nNodes = 256;
    int nf4 = nNodes * 10;

    const float4* xin = (const float4*)(x + (size_t)base * 40);
    for (int i = threadIdx.x; i < nf4; i += 256) ((float4*)sx)[i] = xin[i];
    __syncthreads();

    int t = threadIdx.x;
    if (t < nNodes) {
        float* b = sx + t * 40;
        float ss = 0.f, vs = 0.f;
#pragma unroll
        for (int i = 0; i < 16; i++) ss = fmaf(b[i], b[i], ss);
#pragma unroll
        for (int i = 16; i < 40; i++) vs = fmaf(b[i], b[i], vs);
        float inv_s = rsqrtf(ss * 0.0625f + 1e-8f);
        float inv_v = rsqrtf(vs * 0.125f  + 1e-8f);
#pragma unroll
        for (int i = 0; i < 16; i++) b[i] *= inv_s;
#pragma unroll
        for (int i = 16; i < 40; i++) b[i] *= inv_v;
    }
    __syncthreads();
    float4* xout = (float4*)(g_xnorm + (size_t)base * 40);
    for (int i = threadIdx.x; i < nf4; i += 256) xout[i] = ((float4*)sx)[i];
}

// ---------------------------------------------------------------------------
// Kernel 2: HMMA edge kernel. CTA = 512 edges, 16 warps (R12 epilogue
// structure; chunked MLP to hold register pressure under 128).
// ---------------------------------------------------------------------------
__global__ void __launch_bounds__(512, 1)
k_edge_mma(const int*   __restrict__ esrc,  const int*   __restrict__ edst,
           const float* __restrict__ esh,   const float* __restrict__ erbf,
           const float* __restrict__ elen,
           const float* __restrict__ wr1,   const float* __restrict__ br1,
           const float* __restrict__ br2g,
           const float* __restrict__ wg1,   const float* __restrict__ bg1,
           const float* __restrict__ wg2,   const float* __restrict__ bg2,
           int E, int nN)
{
    extern __shared__ __align__(16) u32 dynsm[];
    u32*   sB32  = dynsm + OFF_B;
    u32*   sA32  = dynsm + OFF_A;
    __nv_bfloat16* sCF = (__nv_bfloat16*)(dynsm + OFF_CF);
    float* sSh   = (float*)(dynsm + OFF_SH);
    float* sEw   = (float*)(dynsm + OFF_EW);
    int*   sDst  = (int*)(dynsm + OFF_DST);
    float* sBr2  = (float*)(dynsm + OFF_BR2);
    float* sWr1  = (float*)(dynsm + OFF_WR1);
    float* sWg1  = (float*)(dynsm + OFF_WG1);
    float* sWg2  = (float*)(dynsm + OFF_WG2);
    float* sBr1  = (float*)(dynsm + OFF_BR1);
    float* sBg1  = (float*)(dynsm + OFF_BG1);

    const int tid  = threadIdx.x;
    const int lane = tid & 31;
    const int wid  = tid >> 5;
    const int g    = lane >> 2;
    const int tig  = lane & 3;

    // ---- stage B (bf16 W2^T) into padded rows
    {
        const uint4* src = (const uint4*)g_w2bf;
        for (int i = tid; i < 4608; i += 512) {
            int j = i >> 3, q = i & 7;
            *(uint4*)(sB32 + j * 36 + q * 4) = src[i];
        }
    }
    if (tid < 512) { sWr1[tid] = wr1[tid]; sWg1[tid] = wg1[tid]; }
    if (tid < 64)  { sWg2[tid] = wg2[tid]; sBr1[tid] = br1[tid]; sBg1[tid] = bg1[tid]; }
    for (int i = tid; i < 576; i += 512) sBr2[i] = br2g[i];

    // ---- per-edge data loads
    int e = blockIdx.x * 512 + tid;
    bool valid = e < E;
    int ec = valid ? e : (E - 1);
    int src_n = esrc[ec];
    int dst_n = edst[ec];
    float4 sh4 = ((const float4*)esh)[ec];
    const float sh0 = sh4.x, s1x = sh4.y, s1y = sh4.z, s1z = sh4.w;
    float len = elen[ec];

    float rb[8];
    {
        const float4* rp = (const float4*)(erbf + (size_t)ec * 8);
        float4 r0 = rp[0], r1 = rp[1];
        rb[0] = r0.x; rb[1] = r0.y; rb[2] = r0.z; rb[3] = r0.w;
        rb[4] = r1.x; rb[5] = r1.y; rb[6] = r1.z; rb[7] = r1.w;
    }

    __syncthreads();   // weights staged before use

    // ---- chunked hidden MLPs: 8 h-values at a time, stream into A tile
    float z = 0.f;
    {
        u32* arow = sA32 + tid * 36;
#pragma unroll
        for (int c = 0; c < 8; c++) {
            float Hc[8], Gc[8];
#pragma unroll
            for (int k = 0; k < 8; k++) { Hc[k] = sBr1[c*8 + k]; Gc[k] = sBg1[c*8 + k]; }
#pragma unroll
            for (int r = 0; r < 8; r++) {
                float rv = rb[r];
                const float4* wa = (const float4*)(sWr1 + r*64 + c*8);
                const float4* wb = (const float4*)(sWg1 + r*64 + c*8);
                float4 a0 = wa[0], a1 = wa[1];
                float4 b0 = wb[0], b1 = wb[1];
                Hc[0] = fmaf(rv, a0.x, Hc[0]); Hc[1] = fmaf(rv, a0.y, Hc[1]);
                Hc[2] = fmaf(rv, a0.z, Hc[2]); Hc[3] = fmaf(rv, a0.w, Hc[3]);
                Hc[4] = fmaf(rv, a1.x, Hc[4]); Hc[5] = fmaf(rv, a1.y, Hc[5]);
                Hc[6] = fmaf(rv, a1.z, Hc[6]); Hc[7] = fmaf(rv, a1.w, Hc[7]);
                Gc[0] = fmaf(rv, b0.x, Gc[0]); Gc[1] = fmaf(rv, b0.y, Gc[1]);
                Gc[2] = fmaf(rv, b0.z, Gc[2]); Gc[3] = fmaf(rv, b0.w, Gc[3]);
                Gc[4] = fmaf(rv, b1.x, Gc[4]); Gc[5] = fmaf(rv, b1.y, Gc[5]);
                Gc[6] = fmaf(rv, b1.z, Gc[6]); Gc[7] = fmaf(rv, b1.w, Gc[7]);
            }
#pragma unroll
            for (int k = 0; k < 8; k++) { float h = Hc[k]; Hc[k] = h * sigf(h); }
            u32 w0 = pack_bf2(Hc[0], Hc[1]);
            u32 w1 = pack_bf2(Hc[2], Hc[3]);
            u32 w2 = pack_bf2(Hc[4], Hc[5]);
            u32 w3 = pack_bf2(Hc[6], Hc[7]);
            *(uint4*)(arow + c * 4) = make_uint4(w0, w1, w2, w3);
#pragma unroll
            for (int k = 0; k < 8; k++) {
                float gg = Gc[k];
                z = fmaf(gg * sigf(gg), sWg2[c*8 + k], z);
            }
        }
    }
    float gw = sigf(z + bg2[0]);
    float cw = (len < CUTOFF) ? 0.5f * (cosf(PI_OVER_C * len) + 1.0f) : 0.0f;
    float ew = (valid ? cw * gw : 0.0f);

    // ---- per-edge coefficients
    {
        float xe[40];
        const float4* xr = (const float4*)(g_xnorm + (size_t)src_n * 40);
#pragma unroll
        for (int q = 0; q < 10; q++) ((float4*)xe)[q] = xr[q];

#pragma unroll
        for (int i = 0; i < 16; i++) sCF[i * 512 + tid] = __float2bfloat16_rn(xe[i]);         // xs
#pragma unroll
        for (int i = 0; i < 24; i++) sCF[(16 + i) * 512 + tid] = __float2bfloat16_rn(xe[16 + i]); // xv
#pragma unroll
        for (int i = 0; i < 8; i++)                                                           // bcoef
            sCF[(40 + i) * 512 + tid] = __float2bfloat16_rn(
                INV_SQRT3 * (xe[16 + 3*i] * s1x + xe[17 + 3*i] * s1y + xe[18 + 3*i] * s1z));
        sSh[0 * 512 + tid] = sh0;
        sSh[1 * 512 + tid] = s1x;
        sSh[2 * 512 + tid] = s1y;
        sSh[3 * 512 + tid] = s1z;
        sEw[tid] = ew;
        sDst[tid] = valid ? dst_n : 0;
    }
    __syncthreads();

    // ---- warp GEMM + fragment epilogue (rt-serial, R12 structure)
    float* agg1 = g_agg + (size_t)nN * 16;
    float* nrmp = g_agg + (size_t)nN * 40;

#pragma unroll 1
    for (int rt = 0; rt < 2; rt++) {
        int e0 = wid * 32 + rt * 16 + g;
        int e1 = e0 + 8;

        float sh0_0 = sSh[e0], sh0_1 = sSh[e1];

        u32 afr[16];
        {
            const u32* a0p = sA32 + (size_t)e0 * 36;
            const u32* a1p = sA32 + (size_t)e1 * 36;
#pragma unroll
            for (int ks = 0; ks < 4; ks++) {
                afr[ks*4+0] = a0p[tig + ks*8];
                afr[ks*4+1] = a1p[tig + ks*8];
                afr[ks*4+2] = a0p[tig + 4 + ks*8];
                afr[ks*4+3] = a1p[tig + 4 + ks*8];
            }
        }

        float am0a[4] = {0,0,0,0}, am0b[4] = {0,0,0,0};
        float aU0 = 0.f, aU1 = 0.f, bU0 = 0.f, bU1 = 0.f;
        float am1a[6] = {0,0,0,0,0,0}, am1b[6] = {0,0,0,0,0,0};

#define TILE8(CT, D0, D1, D2, D3) do {                                   \
        D0 = 0.f; D1 = 0.f; D2 = 0.f; D3 = 0.f;                          \
        const u32* brow_ = sB32 + (size_t)((CT) * 8 + g) * 36;           \
        _Pragma("unroll")                                                \
        for (int ks_ = 0; ks_ < 4; ks_++) {                              \
            u32 bb0_ = brow_[tig + ks_*8];                               \
            u32 bb1_ = brow_[tig + 4 + ks_*8];                           \
            mma_bf16(D0, D1, D2, D3,                                     \
                     afr[ks_*4], afr[ks_*4+1], afr[ks_*4+2], afr[ks_*4+3], \
                     bb0_, bb1_);                                        \
        }                                                                \
    } while (0)

        // ===== m0 region part 1: i = 0..15, cf = xs_i * sh0 =====
#pragma unroll 1
        for (int i = 0; i < 16; i++) {
            float cf0 = bf2f(sCF[i * 512 + e0]) * sh0_0;
            float cf1 = bf2f(sCF[i * 512 + e1]) * sh0_1;
            {
                float d0, d1, d2, d3;
                TILE8(2*i, d0, d1, d2, d3);
                int J0 = i * 16 + 2 * tig;
                float2 bias = *(const float2*)(sBr2 + J0);
                am0a[0] = fmaf(cf0, d0 + bias.x, am0a[0]);
                am0a[1] = fmaf(cf0, d1 + bias.y, am0a[1]);
                am0b[0] = fmaf(cf1, d2 + bias.x, am0b[0]);
                am0b[1] = fmaf(cf1, d3 + bias.y, am0b[1]);
            }
            {
                float d0, d1, d2, d3;
                TILE8(2*i + 1, d0, d1, d2, d3);
                int J0 = i * 16 + 8 + 2 * tig;
                float2 bias = *(const float2*)(sBr2 + J0);
                am0a[2] = fmaf(cf0, d0 + bias.x, am0a[2]);
                am0a[3] = fmaf(cf0, d1 + bias.y, am0a[3]);
                am0b[2] = fmaf(cf1, d2 + bias.x, am0b[2]);
                am0b[3] = fmaf(cf1, d3 + bias.y, am0b[3]);
            }
        }

        // ===== m0 region part 2: i = 16..23, cf = bcoef[i-16] =====
#pragma unroll 1
        for (int i = 16; i < 24; i++) {
            float cf0 = bf2f(sCF[(24 + i) * 512 + e0]);   // row 40+(i-16)
            float cf1 = bf2f(sCF[(24 + i) * 512 + e1]);
            {
                float d0, d1, d2, d3;
                TILE8(2*i, d0, d1, d2, d3);
                int J0 = i * 16 + 2 * tig;
                float2 bias = *(const float2*)(sBr2 + J0);
                am0a[0] = fmaf(cf0, d0 + bias.x, am0a[0]);
                am0a[1] = fmaf(cf0, d1 + bias.y, am0a[1]);
                am0b[0] = fmaf(cf1, d2 + bias.x, am0b[0]);
                am0b[1] = fmaf(cf1, d3 + bias.y, am0b[1]);
            }
            {
                float d0, d1, d2, d3;
                TILE8(2*i + 1, d0, d1, d2, d3);
                int J0 = i * 16 + 8 + 2 * tig;
                float2 bias = *(const float2*)(sBr2 + J0);
                am0a[2] = fmaf(cf0, d0 + bias.x, am0a[2]);
                am0a[3] = fmaf(cf0, d1 + bias.y, am0a[3]);
                am0b[2] = fmaf(cf1, d2 + bias.x, am0b[2]);
                am0b[3] = fmaf(cf1, d3 + bias.y, am0b[3]);
            }
        }

        // ===== w3 region: cols 384..511 (i = 0..15, ct = 48+i), cf = xs_i =====
#pragma unroll 1
        for (int i = 0; i < 16; i++) {
            float xs0 = bf2f(sCF[i * 512 + e0]);
            float xs1 = bf2f(sCF[i * 512 + e1]);
            float d0, d1, d2, d3;
            TILE8(48 + i, d0, d1, d2, d3);
            int J0 = 384 + i * 8 + 2 * tig;
            float2 bias = *(const float2*)(sBr2 + J0);
            aU0 = fmaf(xs0, d0 + bias.x, aU0);
            aU1 = fmaf(xs0, d1 + bias.y, aU1);
            bU0 = fmaf(xs1, d2 + bias.x, bU0);
            bU1 = fmaf(xs1, d3 + bias.y, bU1);
        }

        // ===== w4 region: cols 512..575 (i = 0..7, ct = 64+i), pv = xv*sh0 =====
#pragma unroll 1
        for (int i = 0; i < 8; i++) {
            float d0, d1, d2, d3;
            TILE8(64 + i, d0, d1, d2, d3);
            int J0 = 512 + i * 8 + 2 * tig;
            float2 bias = *(const float2*)(sBr2 + J0);
            float p0x = bf2f(sCF[(16 + 3*i + 0) * 512 + e0]) * sh0_0;
            float p0y = bf2f(sCF[(16 + 3*i + 1) * 512 + e0]) * sh0_0;
            float p0z = bf2f(sCF[(16 + 3*i + 2) * 512 + e0]) * sh0_0;
            float p1x = bf2f(sCF[(16 + 3*i + 0) * 512 + e1]) * sh0_1;
            float p1y = bf2f(sCF[(16 + 3*i + 1) * 512 + e1]) * sh0_1;
            float p1z = bf2f(sCF[(16 + 3*i + 2) * 512 + e1]) * sh0_1;
            float t0 = d0 + bias.x, t1 = d1 + bias.y;
            float t2 = d2 + bias.x, t3 = d3 + bias.y;
            am1a[0] = fmaf(p0x, t0, am1a[0]);
            am1a[1] = fmaf(p0y, t0, am1a[1]);
            am1a[2] = fmaf(p0z, t0, am1a[2]);
            am1a[3] = fmaf(p0x, t1, am1a[3]);
            am1a[4] = fmaf(p0y, t1, am1a[4]);
            am1a[5] = fmaf(p0z, t1, am1a[5]);
            am1b[0] = fmaf(p1x, t2, am1b[0]);
            am1b[1] = fmaf(p1y, t2, am1b[1]);
            am1b[2] = fmaf(p1z, t2, am1b[2]);
            am1b[3] = fmaf(p1x, t3, am1b[3]);
            am1b[4] = fmaf(p1y, t3, am1b[4]);
            am1b[5] = fmaf(p1z, t3, am1b[5]);
        }
#undef TILE8

        // fold U (w3 path) into m1 with each edge's sh1
        {
            float sx = sSh[512 + e0], sy = sSh[1024 + e0], sz = sSh[1536 + e0];
            am1a[0] = fmaf(aU0, sx, am1a[0]);
            am1a[1] = fmaf(aU0, sy, am1a[1]);
            am1a[2] = fmaf(aU0, sz, am1a[2]);
            am1a[3] = fmaf(aU1, sx, am1a[3]);
            am1a[4] = fmaf(aU1, sy, am1a[4]);
            am1a[5] = fmaf(aU1, sz, am1a[5]);
            sx = sSh[512 + e1]; sy = sSh[1024 + e1]; sz = sSh[1536 + e1];
            am1b[0] = fmaf(bU0, sx, am1b[0]);
            am1b[1] = fmaf(bU0, sy, am1b[1]);
            am1b[2] = fmaf(bU0, sz, am1b[2]);
            am1b[3] = fmaf(bU1, sx, am1b[3]);
            am1b[4] = fmaf(bU1, sy, am1b[4]);
            am1b[5] = fmaf(bU1, sz, am1b[5]);
        }

        // ---- scatter (lane-local slots)
        {
            float ew0 = sEw[e0];
            float ew1 = sEw[e1];
            int   dA  = sDst[e0];
            int   dB  = sDst[e1];
            float ca = A_PATH * ew0;
            float cb = A_PATH * ew1;
            int j0 = 2 * tig;

            float* base0 = g_agg + (size_t)dA * 16;
            atomicAdd(base0 + j0,     ca * am0a[0]);
            atomicAdd(base0 + j0 + 1, ca * am0a[1]);
            atomicAdd(base0 + j0 + 8, ca * am0a[2]);
            atomicAdd(base0 + j0 + 9, ca * am0a[3]);
            float* base1 = g_agg + (size_t)dB * 16;
            atomicAdd(base1 + j0,     cb * am0b[0]);
            atomicAdd(base1 + j0 + 1, cb * am0b[1]);
            atomicAdd(base1 + j0 + 8, cb * am0b[2]);
            atomicAdd(base1 + j0 + 9, cb * am0b[3]);

            float* v0 = agg1 + (size_t)dA * 24;
            float* v1 = agg1 + (size_t)dB * 24;
#pragma unroll
            for (int c = 0; c < 3; c++) {
                atomicAdd(v0 + 3*j0 + c,     ca * am1a[c]);
                atomicAdd(v0 + 3*(j0+1) + c, ca * am1a[3+c]);
                atomicAdd(v1 + 3*j0 + c,     cb * am1b[c]);
                atomicAdd(v1 + 3*(j0+1) + c, cb * am1b[3+c]);
            }
            if (tig == 0) {
                atomicAdd(nrmp + dA, ew0);
                atomicAdd(nrmp + dB, ew1);
            }
        }
    }
}

// ---------------------------------------------------------------------------
// Kernel 3: node update (gates + small matmuls + residual)
// ---------------------------------------------------------------------------
__global__ void __launch_bounds__(256)
k_node(const float* __restrict__ x,
       const float* __restrict__ Wms, const float* __restrict__ Wmv,
       const float* __restrict__ Wus, const float* __restrict__ Wuv,
       const float* __restrict__ Wss, const float* __restrict__ Wsv,
       const float* __restrict__ rsp,
       float* __restrict__ out, int nN)
{
    __shared__ float sWms[384], sWmv[64], sWus[256], sWuv[64], sWss[256], sWsv[64];
    int t = threadIdx.x;
    for (int i = t; i < 384; i += blockDim.x) sWms[i] = Wms[i];
    for (int i = t; i < 256; i += blockDim.x) { sWus[i] = Wus[i]; sWss[i] = Wss[i]; }
    for (int i = t; i < 64;  i += blockDim.x) { sWmv[i] = Wmv[i]; sWuv[i] = Wuv[i]; sWsv[i] = Wsv[i]; }
    __syncthreads();

    int n = blockIdx.x * blockDim.x + t;
    if (n >= nN) return;

    float rs = rsp[0];
    float nrm = fmaxf(g_agg[(size_t)nN * 40 + n], 1e-8f);
    float inv = __fdividef(1.0f, nrm);

    float a0[16], a1[24];
    {
        const float4* p0 = (const float4*)(g_agg + (size_t)n * 16);
#pragma unroll
        for (int q = 0; q < 4; q++) ((float4*)a0)[q] = p0[q];
        const float4* p1 = (const float4*)(g_agg + (size_t)nN * 16 + (size_t)n * 24);
#pragma unroll
        for (int q = 0; q < 6; q++) ((float4*)a1)[q] = p1[q];
    }
#pragma unroll
    for (int j = 0; j < 16; j++) a0[j] *= inv;
#pragma unroll
    for (int j = 0; j < 24; j++) a1[j] *= inv;

    float sc[24];
#pragma unroll
    for (int j = 0; j < 24; j++) sc[j] = 0.f;
#pragma unroll
    for (int i = 0; i < 16; i++) {
        float ai = a0[i];
#pragma unroll
        for (int j = 0; j < 24; j++) sc[j] = fmaf(ai, sWms[i * 24 + j], sc[j]);
    }

    float scal[16], gate[8];
#pragma unroll
    for (int j = 0; j < 16; j++) { float v = 0.25f * sc[j]; scal[j] = v * sigf(v); }
#pragma unroll
    for (int j = 0; j < 8;  j++) gate[j] = sigf(0.25f * sc[16 + j]);

    float vg[24];
#pragma unroll
    for (int j = 0; j < 8; j++) {
#pragma unroll
        for (int c = 0; c < 3; c++) {
            float acc = 0.f;
#pragma unroll
            for (int i = 0; i < 8; i++) acc = fmaf(a1[i * 3 + c], sWmv[i * 8 + j], acc);
            vg[3 * j + c] = acc * INV_SQRT8 * gate[j];
        }
    }

    float xs[16], xv[24];
    {
        const float4* xn = (const float4*)(g_xnorm + (size_t)n * 40);
#pragma unroll
        for (int q = 0; q < 4; q++) ((float4*)xs)[q] = xn[q];
#pragma unroll
        for (int q = 0; q < 6; q++) ((float4*)xv)[q] = xn[4 + q];
    }

    float xi[40];
    {
        const float4* xp = (const float4*)(x + (size_t)n * 40);
#pragma unroll
        for (int q = 0; q < 10; q++) ((float4*)xi)[q] = xp[q];
    }

    float ob[40];
#pragma unroll
    for (int j = 0; j < 16; j++) {
        float acc = 0.f;
#pragma unroll
        for (int i = 0; i < 16; i++) {
            acc = fmaf(scal[i], sWus[i * 16 + j], acc);
            acc = fmaf(xs[i],   sWss[i * 16 + j], acc);
        }
        ob[j] = xi[j] + rs * 0.25f * acc;
    }
#pragma unroll
    for (int j = 0; j < 8; j++) {
#pragma unroll
        for (int c = 0; c < 3; c++) {
            float acc = 0.f;
#pragma unroll
            for (int i = 0; i < 8; i++) {
                acc = fmaf(vg[3 * i + c], sWuv[i * 8 + j], acc);
                acc = fmaf(xv[3 * i + c], sWsv[i * 8 + j], acc);
            }
            ob[16 + 3 * j + c] = xi[16 + 3 * j + c] + rs * INV_SQRT8 * acc;
        }
    }

    float4* o = (float4*)(out + (size_t)n * 40);
#pragma unroll
    for (int q = 0; q < 10; q++) o[q] = ((float4*)ob)[q];
}

// ---------------------------------------------------------------------------
// Launch
// ---------------------------------------------------------------------------
extern "C" void kernel_launch(void* const* d_in, const int* in_sizes, int n_in,
                              void* d_out, int out_size)
{
    const float* x    = (const float*)d_in[0];
    const int*   esrc = (const int*)  d_in[1];
    const int*   edst = (const int*)  d_in[2];
    const float* esh  = (const float*)d_in[3];
    const float* erbf = (const float*)d_in[4];
    const float* elen = (const float*)d_in[5];
    const float* wr1  = (const float*)d_in[6];
    const float* br1  = (const float*)d_in[7];
    const float* wr2  = (const float*)d_in[8];
    const float* br2  = (const float*)d_in[9];
    const float* wg1  = (const float*)d_in[10];
    const float* bg1  = (const float*)d_in[11];
    const float* wg2  = (const float*)d_in[12];
    const float* bg2  = (const float*)d_in[13];
    const float* Wms  = (const float*)d_in[14];
    const float* Wmv  = (const float*)d_in[15];
    const float* Wus  = (const float*)d_in[16];
    const float* Wuv  = (const float*)d_in[17];
    const float* Wss  = (const float*)d_in[18];
    const float* Wsv  = (const float*)d_in[19];
    const float* rsp  = (const float*)d_in[20];

    int nN = in_sizes[0] / 40;
    int E  = in_sizes[1];
    float* out = (float*)d_out;

    size_t shbytes = (size_t)SMEM_U32 * 4u;   // 225280 B
    cudaFuncSetAttribute(k_edge_mma, cudaFuncAttributeMaxDynamicSharedMemorySize, (int)shbytes);

    k_prep<<<(36864 + 255) / 256, 256>>>(wr2);
    int totalz = nN * 41;
    k_zero<<<(totalz / 4 + 255) / 256, 256>>>(totalz);
    k_norm<<<(nN + 255) / 256, 256>>>(x, nN);
    k_edge_mma<<<(E + 511) / 512, 512, shbytes>>>(esrc, edst, esh, erbf, elen,
                                                  wr1, br1, br2,
                                                  wg1, bg1, wg2, bg2, E, nN);
    k_node<<<(nN + 255) / 256, 256>>>(x, Wms, Wmv, Wus, Wuv, Wss, Wsv, rsp, out, nN);
}

// round 16
// speedup vs baseline: 1.7555x; 1.0603x over previous
#include <cuda_runtime.h>
#include <cuda_bf16.h>
#include <math.h>

typedef unsigned int u32;

// ---------------------------------------------------------------------------
// Problem constants
// ---------------------------------------------------------------------------
#define CUTOFF     5.0f
#define A_PATH     0.20412414523193150818f   // 1/sqrt(24)
#define INV_SQRT3  0.57735026918962576451f
#define INV_SQRT8  0.35355339059327376220f
#define PI_OVER_C  0.62831853071795864769f   // pi / 5

#define NNMAX 50000
__device__ float g_xnorm[NNMAX * 40];
__device__ float g_agg[NNMAX * 41];                      // agg0 | agg1 | norm
__device__ __align__(16) unsigned short g_w2bf[36864];   // W2^T bf16, [j][h] row-major

// smem layout (u32 offsets)
#define OFF_B    0        // 20736 : W2^T bf16 rows of 36 u32 (144 B row stride)
#define OFF_A    20736    // 18432 : A tile, 512 rows of 36 u32
#define OFF_CF   39168    // 12288 : bf16[48][512]  xs(0..15) xv(16..39) bcoef(40..47)
#define OFF_SH   51456    //  2048 : fp32[4][512]   sh0 s1x s1y s1z
#define OFF_EW   53504    //   512 : fp32 ew
#define OFF_DST  54016    //   512 : int dst
#define OFF_BR2  54528    //   576
#define OFF_WR1  55104    //   512
#define OFF_WG1  55616    //   512
#define OFF_WG2  56128    //    64
#define OFF_BR1  56192    //    64
#define OFF_BG1  56256    //    64
#define SMEM_U32 56320    // 225280 bytes

__device__ __forceinline__ float sigf(float x) {
    return __fdividef(1.0f, 1.0f + __expf(-x));
}

// m16n8k16 bf16 MMA, fp32 accumulate (baseline PTX, works on plain sm_103)
__device__ __forceinline__ void mma_bf16(float& d0, float& d1, float& d2, float& d3,
                                         u32 a0, u32 a1, u32 a2, u32 a3,
                                         u32 b0, u32 b1)
{
    asm volatile(
        "mma.sync.aligned.m16n8k16.row.col.f32.bf16.bf16.f32 "
        "{%0,%1,%2,%3}, {%4,%5,%6,%7}, {%8,%9}, {%0,%1,%2,%3};"
        : "+f"(d0), "+f"(d1), "+f"(d2), "+f"(d3)
        : "r"(a0), "r"(a1), "r"(a2), "r"(a3), "r"(b0), "r"(b1));
}

// ldmatrix x4 (PTX 6.5, sm_75+ baseline)
__device__ __forceinline__ void ldm4(u32& r0, u32& r1, u32& r2, u32& r3, u32 addr)
{
    asm volatile("ldmatrix.sync.aligned.m8n8.x4.shared.b16 {%0,%1,%2,%3}, [%4];"
                 : "=r"(r0), "=r"(r1), "=r"(r2), "=r"(r3) : "r"(addr));
}

__device__ __forceinline__ u32 smem_u32(const void* p) {
    u32 a;
    asm("{ .reg .u64 t; cvta.to.shared.u64 t, %1; cvt.u32.u64 %0, t; }" : "=r"(a) : "l"(p));
    return a;
}

__device__ __forceinline__ u32 pack_bf2(float a, float b) {
    return (u32)__bfloat16_as_ushort(__float2bfloat16_rn(a))
         | ((u32)__bfloat16_as_ushort(__float2bfloat16_rn(b)) << 16);
}
__device__ __forceinline__ float bf2f(__nv_bfloat16 v) { return __bfloat162float(v); }

// ---------------------------------------------------------------------------
// Kernel P: W2 -> bf16 transposed  g_w2bf[j*64+h] = bf16(wr2[h*576+j])
// ---------------------------------------------------------------------------
__global__ void k_prep(const float* __restrict__ wr2)
{
    int idx = blockIdx.x * blockDim.x + threadIdx.x;
    if (idx >= 36864) return;
    int j = idx >> 6, h = idx & 63;
    g_w2bf[idx] = __bfloat16_as_ushort(__float2bfloat16_rn(wr2[h * 576 + j]));
}

// ---------------------------------------------------------------------------
// Kernel 0: zero aggregation scratch
// ---------------------------------------------------------------------------
__global__ void k_zero(int total)
{
    int i = blockIdx.x * blockDim.x + threadIdx.x;
    int nf4 = total >> 2;
    float4 z = make_float4(0.f, 0.f, 0.f, 0.f);
    if (i < nf4) ((float4*)g_agg)[i] = z;
    if (i < (total & 3)) g_agg[(nf4 << 2) + i] = 0.f;
}

// ---------------------------------------------------------------------------
// Kernel 1: irrep norm
// ---------------------------------------------------------------------------
__global__ void __launch_bounds__(256)
k_norm(const float* __restrict__ x, int nN)
{
    __shared__ float sx[256 * 40];
    int base = blockIdx.x * 256;
    int nNodes = nN - base; if (nNodes > 256) nNodes = 256;
    int nf4 = nNodes * 10;

    const float4* xin = (const float4*)(x + (size_t)base * 40);
    for (int i = threadIdx.x; i < nf4; i += 256) ((float4*)sx)[i] = xin[i];
    __syncthreads();

    int t = threadIdx.x;
    if (t < nNodes) {
        float* b = sx + t * 40;
        float ss = 0.f, vs = 0.f;
#pragma unroll
        for (int i = 0; i < 16; i++) ss = fmaf(b[i], b[i], ss);
#pragma unroll
        for (int i = 16; i < 40; i++) vs = fmaf(b[i], b[i], vs);
        float inv_s = rsqrtf(ss * 0.0625f + 1e-8f);
        float inv_v = rsqrtf(vs * 0.125f  + 1e-8f);
#pragma unroll
        for (int i = 0; i < 16; i++) b[i] *= inv_s;
#pragma unroll
        for (int i = 16; i < 40; i++) b[i] *= inv_v;
    }
    __syncthreads();
    float4* xout = (float4*)(g_xnorm + (size_t)base * 40);
    for (int i = threadIdx.x; i < nf4; i += 256) xout[i] = ((float4*)sx)[i];
}

// ---------------------------------------------------------------------------
// Kernel 2: HMMA edge kernel. CTA = 512 edges, 16 warps.
//   ldmatrix fragment loads + paired-tile MMA chains for 2x ILP.
// ---------------------------------------------------------------------------
__global__ void __launch_bounds__(512, 1)
k_edge_mma(const int*   __restrict__ esrc,  const int*   __restrict__ edst,
           const float* __restrict__ esh,   const float* __restrict__ erbf,
           const float* __restrict__ elen,
           const float* __restrict__ wr1,   const float* __restrict__ br1,
           const float* __restrict__ br2g,
           const float* __restrict__ wg1,   const float* __restrict__ bg1,
           const float* __restrict__ wg2,   const float* __restrict__ bg2,
           int E, int nN)
{
    extern __shared__ __align__(16) u32 dynsm[];
    u32*   sB32  = dynsm + OFF_B;
    u32*   sA32  = dynsm + OFF_A;
    __nv_bfloat16* sCF = (__nv_bfloat16*)(dynsm + OFF_CF);
    float* sSh   = (float*)(dynsm + OFF_SH);
    float* sEw   = (float*)(dynsm + OFF_EW);
    int*   sDst  = (int*)(dynsm + OFF_DST);
    float* sBr2  = (float*)(dynsm + OFF_BR2);
    float* sWr1  = (float*)(dynsm + OFF_WR1);
    float* sWg1  = (float*)(dynsm + OFF_WG1);
    float* sWg2  = (float*)(dynsm + OFF_WG2);
    float* sBr1  = (float*)(dynsm + OFF_BR1);
    float* sBg1  = (float*)(dynsm + OFF_BG1);

    const int tid  = threadIdx.x;
    const int lane = tid & 31;
    const int wid  = tid >> 5;
    const int g    = lane >> 2;
    const int tig  = lane & 3;

    // ---- stage B (bf16 W2^T) into padded rows
    {
        const uint4* src = (const uint4*)g_w2bf;
        for (int i = tid; i < 4608; i += 512) {
            int j = i >> 3, q = i & 7;
            *(uint4*)(sB32 + j * 36 + q * 4) = src[i];
        }
    }
    if (tid < 512) { sWr1[tid] = wr1[tid]; sWg1[tid] = wg1[tid]; }
    if (tid < 64)  { sWg2[tid] = wg2[tid]; sBr1[tid] = br1[tid]; sBg1[tid] = bg1[tid]; }
    for (int i = tid; i < 576; i += 512) sBr2[i] = br2g[i];

    // ---- per-edge data loads
    int e = blockIdx.x * 512 + tid;
    bool valid = e < E;
    int ec = valid ? e : (E - 1);
    int src_n = esrc[ec];
    int dst_n = edst[ec];
    float4 sh4 = ((const float4*)esh)[ec];
    const float sh0 = sh4.x, s1x = sh4.y, s1y = sh4.z, s1z = sh4.w;
    float len = elen[ec];

    float rb[8];
    {
        const float4* rp = (const float4*)(erbf + (size_t)ec * 8);
        float4 r0 = rp[0], r1 = rp[1];
        rb[0] = r0.x; rb[1] = r0.y; rb[2] = r0.z; rb[3] = r0.w;
        rb[4] = r1.x; rb[5] = r1.y; rb[6] = r1.z; rb[7] = r1.w;
    }

    __syncthreads();   // weights staged before use

    // ---- chunked hidden MLPs: 8 h-values at a time, stream into A tile
    float z = 0.f;
    {
        u32* arow = sA32 + tid * 36;
#pragma unroll
        for (int c = 0; c < 8; c++) {
            float Hc[8], Gc[8];
#pragma unroll
            for (int k = 0; k < 8; k++) { Hc[k] = sBr1[c*8 + k]; Gc[k] = sBg1[c*8 + k]; }
#pragma unroll
            for (int r = 0; r < 8; r++) {
                float rv = rb[r];
                const float4* wa = (const float4*)(sWr1 + r*64 + c*8);
                const float4* wb = (const float4*)(sWg1 + r*64 + c*8);
                float4 a0 = wa[0], a1 = wa[1];
                float4 b0 = wb[0], b1 = wb[1];
                Hc[0] = fmaf(rv, a0.x, Hc[0]); Hc[1] = fmaf(rv, a0.y, Hc[1]);
                Hc[2] = fmaf(rv, a0.z, Hc[2]); Hc[3] = fmaf(rv, a0.w, Hc[3]);
                Hc[4] = fmaf(rv, a1.x, Hc[4]); Hc[5] = fmaf(rv, a1.y, Hc[5]);
                Hc[6] = fmaf(rv, a1.z, Hc[6]); Hc[7] = fmaf(rv, a1.w, Hc[7]);
                Gc[0] = fmaf(rv, b0.x, Gc[0]); Gc[1] = fmaf(rv, b0.y, Gc[1]);
                Gc[2] = fmaf(rv, b0.z, Gc[2]); Gc[3] = fmaf(rv, b0.w, Gc[3]);
                Gc[4] = fmaf(rv, b1.x, Gc[4]); Gc[5] = fmaf(rv, b1.y, Gc[5]);
                Gc[6] = fmaf(rv, b1.z, Gc[6]); Gc[7] = fmaf(rv, b1.w, Gc[7]);
            }
#pragma unroll
            for (int k = 0; k < 8; k++) { float h = Hc[k]; Hc[k] = h * sigf(h); }
            u32 w0 = pack_bf2(Hc[0], Hc[1]);
            u32 w1 = pack_bf2(Hc[2], Hc[3]);
            u32 w2 = pack_bf2(Hc[4], Hc[5]);
            u32 w3 = pack_bf2(Hc[6], Hc[7]);
            *(uint4*)(arow + c * 4) = make_uint4(w0, w1, w2, w3);
#pragma unroll
            for (int k = 0; k < 8; k++) {
                float gg = Gc[k];
                z = fmaf(gg * sigf(gg), sWg2[c*8 + k], z);
            }
        }
    }
    float gw = sigf(z + bg2[0]);
    float cw = (len < CUTOFF) ? 0.5f * (cosf(PI_OVER_C * len) + 1.0f) : 0.0f;
    float ew = (valid ? cw * gw : 0.0f);

    // ---- per-edge coefficients
    {
        float xe[40];
        const float4* xr = (const float4*)(g_xnorm + (size_t)src_n * 40);
#pragma unroll
        for (int q = 0; q < 10; q++) ((float4*)xe)[q] = xr[q];

#pragma unroll
        for (int i = 0; i < 16; i++) sCF[i * 512 + tid] = __float2bfloat16_rn(xe[i]);             // xs
#pragma unroll
        for (int i = 0; i < 24; i++) sCF[(16 + i) * 512 + tid] = __float2bfloat16_rn(xe[16 + i]); // xv
#pragma unroll
        for (int i = 0; i < 8; i++)                                                               // bcoef
            sCF[(40 + i) * 512 + tid] = __float2bfloat16_rn(
                INV_SQRT3 * (xe[16 + 3*i] * s1x + xe[17 + 3*i] * s1y + xe[18 + 3*i] * s1z));
        sSh[0 * 512 + tid] = sh0;
        sSh[1 * 512 + tid] = s1x;
        sSh[2 * 512 + tid] = s1y;
        sSh[3 * 512 + tid] = s1z;
        sEw[tid] = ew;
        sDst[tid] = valid ? dst_n : 0;
    }
    __syncthreads();

    // ---- warp GEMM + fragment epilogue (rt-serial; paired-tile chains)
    float* agg1 = g_agg + (size_t)nN * 16;
    float* nrmp = g_agg + (size_t)nN * 40;

    // lane-constant ldmatrix address components (bytes)
    const u32 bBase = smem_u32(sB32) + (u32)(lane & 7) * 144u + (u32)(lane >> 3) * 16u;
    const u32 aBase = smem_u32(sA32) + ((u32)((lane >> 3) & 1)) * 1152u
                    + (u32)(lane & 7) * 144u + (u32)(lane >> 4) * 16u;

#pragma unroll 1
    for (int rt = 0; rt < 2; rt++) {
        int e0 = wid * 32 + rt * 16 + g;
        int e1 = e0 + 8;

        float sh0_0 = sSh[e0], sh0_1 = sSh[e1];

        // A fragments for this 16-row tile: 4 ldmatrix.x4
        u32 afr[16];
        {
            u32 aAddr = aBase + (u32)(wid * 32 + rt * 16) * 144u;
#pragma unroll
            for (int ks = 0; ks < 4; ks++)
                ldm4(afr[ks*4+0], afr[ks*4+1], afr[ks*4+2], afr[ks*4+3], aAddr + (u32)ks * 32u);
        }

        float am0a[4] = {0,0,0,0}, am0b[4] = {0,0,0,0};
        float aU0 = 0.f, aU1 = 0.f, bU0 = 0.f, bU1 = 0.f;
        float am1a[6] = {0,0,0,0,0,0}, am1b[6] = {0,0,0,0,0,0};

        // pair of tiles ct, ct+1 -> two interleaved MMA chains
#define TILE_PAIR(CT, DA0,DA1,DA2,DA3, DB0,DB1,DB2,DB3) do {             \
        u32 b0_[8], b1_[8];                                              \
        u32 ad_ = bBase + (u32)(CT) * 1152u;                             \
        ldm4(b0_[0], b0_[1], b0_[2], b0_[3], ad_);                       \
        ldm4(b0_[4], b0_[5], b0_[6], b0_[7], ad_ + 64u);                 \
        ldm4(b1_[0], b1_[1], b1_[2], b1_[3], ad_ + 1152u);               \
        ldm4(b1_[4], b1_[5], b1_[6], b1_[7], ad_ + 1216u);               \
        DA0=0.f; DA1=0.f; DA2=0.f; DA3=0.f;                              \
        DB0=0.f; DB1=0.f; DB2=0.f; DB3=0.f;                              \
        _Pragma("unroll")                                                \
        for (int ks_ = 0; ks_ < 4; ks_++) {                              \
            mma_bf16(DA0,DA1,DA2,DA3,                                    \
                     afr[ks_*4], afr[ks_*4+1], afr[ks_*4+2], afr[ks_*4+3], \
                     b0_[2*ks_], b0_[2*ks_+1]);                          \
            mma_bf16(DB0,DB1,DB2,DB3,                                    \
                     afr[ks_*4], afr[ks_*4+1], afr[ks_*4+2], afr[ks_*4+3], \
                     b1_[2*ks_], b1_[2*ks_+1]);                          \
        }                                                                \
    } while (0)

        // ===== m0 region part 1: i = 0..15, cf = xs_i * sh0; tiles 2i, 2i+1 =====
#pragma unroll 1
        for (int i = 0; i < 16; i++) {
            float cf0 = bf2f(sCF[i * 512 + e0]) * sh0_0;
            float cf1 = bf2f(sCF[i * 512 + e1]) * sh0_1;
            float dA0,dA1,dA2,dA3, dB0,dB1,dB2,dB3;
            TILE_PAIR(2*i, dA0,dA1,dA2,dA3, dB0,dB1,dB2,dB3);
            int J0 = i * 16 + 2 * tig;
            float2 biasA = *(const float2*)(sBr2 + J0);
            float2 biasB = *(const float2*)(sBr2 + J0 + 8);
            am0a[0] = fmaf(cf0, dA0 + biasA.x, am0a[0]);
            am0a[1] = fmaf(cf0, dA1 + biasA.y, am0a[1]);
            am0b[0] = fmaf(cf1, dA2 + biasA.x, am0b[0]);
            am0b[1] = fmaf(cf1, dA3 + biasA.y, am0b[1]);
            am0a[2] = fmaf(cf0, dB0 + biasB.x, am0a[2]);
            am0a[3] = fmaf(cf0, dB1 + biasB.y, am0a[3]);
            am0b[2] = fmaf(cf1, dB2 + biasB.x, am0b[2]);
            am0b[3] = fmaf(cf1, dB3 + biasB.y, am0b[3]);
        }

        // ===== m0 region part 2: i = 16..23, cf = bcoef[i-16]; tiles 2i, 2i+1 =====
#pragma unroll 1
        for (int i = 16; i < 24; i++) {
            float cf0 = bf2f(sCF[(24 + i) * 512 + e0]);   // row 40+(i-16)
            float cf1 = bf2f(sCF[(24 + i) * 512 + e1]);
            float dA0,dA1,dA2,dA3, dB0,dB1,dB2,dB3;
            TILE_PAIR(2*i, dA0,dA1,dA2,dA3, dB0,dB1,dB2,dB3);
            int J0 = i * 16 + 2 * tig;
            float2 biasA = *(const float2*)(sBr2 + J0);
            float2 biasB = *(const float2*)(sBr2 + J0 + 8);
            am0a[0] = fmaf(cf0, dA0 + biasA.x, am0a[0]);
            am0a[1] = fmaf(cf0, dA1 + biasA.y, am0a[1]);
            am0b[0] = fmaf(cf1, dA2 + biasA.x, am0b[0]);
            am0b[1] = fmaf(cf1, dA3 + biasA.y, am0b[1]);
            am0a[2] = fmaf(cf0, dB0 + biasB.x, am0a[2]);
            am0a[3] = fmaf(cf0, dB1 + biasB.y, am0a[3]);
            am0b[2] = fmaf(cf1, dB2 + biasB.x, am0b[2]);
            am0b[3] = fmaf(cf1, dB3 + biasB.y, am0b[3]);
        }

        // ===== w3 region: i = 0..15 step 2, tiles 48+i, 49+i; cf = xs_i =====
#pragma unroll 1
        for (int i = 0; i < 16; i += 2) {
            float xsA0 = bf2f(sCF[i * 512 + e0]);
            float xsA1 = bf2f(sCF[i * 512 + e1]);
            float xsB0 = bf2f(sCF[(i + 1) * 512 + e0]);
            float xsB1 = bf2f(sCF[(i + 1) * 512 + e1]);
            float dA0,dA1,dA2,dA3, dB0,dB1,dB2,dB3;
            TILE_PAIR(48 + i, dA0,dA1,dA2,dA3, dB0,dB1,dB2,dB3);
            int J0 = 384 + i * 8 + 2 * tig;
            float2 biasA = *(const float2*)(sBr2 + J0);
            float2 biasB = *(const float2*)(sBr2 + J0 + 8);
            aU0 = fmaf(xsA0, dA0 + biasA.x, aU0);
            aU1 = fmaf(xsA0, dA1 + biasA.y, aU1);
            bU0 = fmaf(xsA1, dA2 + biasA.x, bU0);
            bU1 = fmaf(xsA1, dA3 + biasA.y, bU1);
            aU0 = fmaf(xsB0, dB0 + biasB.x, aU0);
            aU1 = fmaf(xsB0, dB1 + biasB.y, aU1);
            bU0 = fmaf(xsB1, dB2 + biasB.x, bU0);
            bU1 = fmaf(xsB1, dB3 + biasB.y, bU1);
        }

        // ===== w4 region: i = 0..7 step 2, tiles 64+i, 65+i; pv = xv*sh0 =====
#pragma unroll 1
        for (int i = 0; i < 8; i += 2) {
            float dA0,dA1,dA2,dA3, dB0,dB1,dB2,dB3;
            TILE_PAIR(64 + i, dA0,dA1,dA2,dA3, dB0,dB1,dB2,dB3);
            int J0 = 512 + i * 8 + 2 * tig;
            float2 biasA = *(const float2*)(sBr2 + J0);
            float2 biasB = *(const float2*)(sBr2 + J0 + 8);
            {   // tile 64+i
                float p0x = bf2f(sCF[(16 + 3*i + 0) * 512 + e0]) * sh0_0;
                float p0y = bf2f(sCF[(16 + 3*i + 1) * 512 + e0]) * sh0_0;
                float p0z = bf2f(sCF[(16 + 3*i + 2) * 512 + e0]) * sh0_0;
                float p1x = bf2f(sCF[(16 + 3*i + 0) * 512 + e1]) * sh0_1;
                float p1y = bf2f(sCF[(16 + 3*i + 1) * 512 + e1]) * sh0_1;
                float p1z = bf2f(sCF[(16 + 3*i + 2) * 512 + e1]) * sh0_1;
                float t0 = dA0 + biasA.x, t1 = dA1 + biasA.y;
                float t2 = dA2 + biasA.x, t3 = dA3 + biasA.y;
                am1a[0] = fmaf(p0x, t0, am1a[0]);
                am1a[1] = fmaf(p0y, t0, am1a[1]);
                am1a[2] = fmaf(p0z, t0, am1a[2]);
                am1a[3] = fmaf(p0x, t1, am1a[3]);
                am1a[4] = fmaf(p0y, t1, am1a[4]);
                am1a[5] = fmaf(p0z, t1, am1a[5]);
                am1b[0] = fmaf(p1x, t2, am1b[0]);
                am1b[1] = fmaf(p1y, t2, am1b[1]);
                am1b[2] = fmaf(p1z, t2, am1b[2]);
                am1b[3] = fmaf(p1x, t3, am1b[3]);
                am1b[4] = fmaf(p1y, t3, am1b[4]);
                am1b[5] = fmaf(p1z, t3, am1b[5]);
            }
            {   // tile 65+i
                int ii = i + 1;
                float p0x = bf2f(sCF[(16 + 3*ii + 0) * 512 + e0]) * sh0_0;
                float p0y = bf2f(sCF[(16 + 3*ii + 1) * 512 + e0]) * sh0_0;
                float p0z = bf2f(sCF[(16 + 3*ii + 2) * 512 + e0]) * sh0_0;
                float p1x = bf2f(sCF[(16 + 3*ii + 0) * 512 + e1]) * sh0_1;
                float p1y = bf2f(sCF[(16 + 3*ii + 1) * 512 + e1]) * sh0_1;
                float p1z = bf2f(sCF[(16 + 3*ii + 2) * 512 + e1]) * sh0_1;
                float t0 = dB0 + biasB.x, t1 = dB1 + biasB.y;
                float t2 = dB2 + biasB.x, t3 = dB3 + biasB.y;
                am1a[0] = fmaf(p0x, t0, am1a[0]);
                am1a[1] = fmaf(p0y, t0, am1a[1]);
                am1a[2] = fmaf(p0z, t0, am1a[2]);
                am1a[3] = fmaf(p0x, t1, am1a[3]);
                am1a[4] = fmaf(p0y, t1, am1a[4]);
                am1a[5] = fmaf(p0z, t1, am1a[5]);
                am1b[0] = fmaf(p1x, t2, am1b[0]);
                am1b[1] = fmaf(p1y, t2, am1b[1]);
                am1b[2] = fmaf(p1z, t2, am1b[2]);
                am1b[3] = fmaf(p1x, t3, am1b[3]);
                am1b[4] = fmaf(p1y, t3, am1b[4]);
                am1b[5] = fmaf(p1z, t3, am1b[5]);
            }
        }
#undef TILE_PAIR

        // fold U (w3 path) into m1 with each edge's sh1
        {
            float sx = sSh[512 + e0], sy = sSh[1024 + e0], sz = sSh[1536 + e0];
            am1a[0] = fmaf(aU0, sx, am1a[0]);
            am1a[1] = fmaf(aU0, sy, am1a[1]);
            am1a[2] = fmaf(aU0, sz, am1a[2]);
            am1a[3] = fmaf(aU1, sx, am1a[3]);
            am1a[4] = fmaf(aU1, sy, am1a[4]);
            am1a[5] = fmaf(aU1, sz, am1a[5]);
            sx = sSh[512 + e1]; sy = sSh[1024 + e1]; sz = sSh[1536 + e1];
            am1b[0] = fmaf(bU0, sx, am1b[0]);
            am1b[1] = fmaf(bU0, sy, am1b[1]);
            am1b[2] = fmaf(bU0, sz, am1b[2]);
            am1b[3] = fmaf(bU1, sx, am1b[3]);
            am1b[4] = fmaf(bU1, sy, am1b[4]);
            am1b[5] = fmaf(bU1, sz, am1b[5]);
        }

        // ---- scatter (lane-local slots)
        {
            float ew0 = sEw[e0];
            float ew1 = sEw[e1];
            int   dA  = sDst[e0];
            int   dB  = sDst[e1];
            float ca = A_PATH * ew0;
            float cb = A_PATH * ew1;
            int j0 = 2 * tig;

            float* base0 = g_agg + (size_t)dA * 16;
            atomicAdd(base0 + j0,     ca * am0a[0]);
            atomicAdd(base0 + j0 + 1, ca * am0a[1]);
            atomicAdd(base0 + j0 + 8, ca * am0a[2]);
            atomicAdd(base0 + j0 + 9, ca * am0a[3]);
            float* base1 = g_agg + (size_t)dB * 16;
            atomicAdd(base1 + j0,     cb * am0b[0]);
            atomicAdd(base1 + j0 + 1, cb * am0b[1]);
            atomicAdd(base1 + j0 + 8, cb * am0b[2]);
            atomicAdd(base1 + j0 + 9, cb * am0b[3]);

            float* v0 = agg1 + (size_t)dA * 24;
            float* v1 = agg1 + (size_t)dB * 24;
#pragma unroll
            for (int c = 0; c < 3; c++) {
                atomicAdd(v0 + 3*j0 + c,     ca * am1a[c]);
                atomicAdd(v0 + 3*(j0+1) + c, ca * am1a[3+c]);
                atomicAdd(v1 + 3*j0 + c,     cb * am1b[c]);
                atomicAdd(v1 + 3*(j0+1) + c, cb * am1b[3+c]);
            }
            if (tig == 0) {
                atomicAdd(nrmp + dA, ew0);
                atomicAdd(nrmp + dB, ew1);
            }
        }
    }
}

// ---------------------------------------------------------------------------
// Kernel 3: node update (gates + small matmuls + residual)
// ---------------------------------------------------------------------------
__global__ void __launch_bounds__(256)
k_node(const float* __restrict__ x,
       const float* __restrict__ Wms, const float* __restrict__ Wmv,
       const float* __restrict__ Wus, const float* __restrict__ Wuv,
       const float* __restrict__ Wss, const float* __restrict__ Wsv,
       const float* __restrict__ rsp,
       float* __restrict__ out, int nN)
{
    __shared__ float sWms[384], sWmv[64], sWus[256], sWuv[64], sWss[256], sWsv[64];
    int t = threadIdx.x;
    for (int i = t; i < 384; i += blockDim.x) sWms[i] = Wms[i];
    for (int i = t; i < 256; i += blockDim.x) { sWus[i] = Wus[i]; sWss[i] = Wss[i]; }
    for (int i = t; i < 64;  i += blockDim.x) { sWmv[i] = Wmv[i]; sWuv[i] = Wuv[i]; sWsv[i] = Wsv[i]; }
    __syncthreads();

    int n = blockIdx.x * blockDim.x + t;
    if (n >= nN) return;

    float rs = rsp[0];
    float nrm = fmaxf(g_agg[(size_t)nN * 40 + n], 1e-8f);
    float inv = __fdividef(1.0f, nrm);

    float a0[16], a1[24];
    {
        const float4* p0 = (const float4*)(g_agg + (size_t)n * 16);
#pragma unroll
        for (int q = 0; q < 4; q++) ((float4*)a0)[q] = p0[q];
        const float4* p1 = (const float4*)(g_agg + (size_t)nN * 16 + (size_t)n * 24);
#pragma unroll
        for (int q = 0; q < 6; q++) ((float4*)a1)[q] = p1[q];
    }
#pragma unroll
    for (int j = 0; j < 16; j++) a0[j] *= inv;
#pragma unroll
    for (int j = 0; j < 24; j++) a1[j] *= inv;

    float sc[24];
#pragma unroll
    for (int j = 0; j < 24; j++) sc[j] = 0.f;
#pragma unroll
    for (int i = 0; i < 16; i++) {
        float ai = a0[i];
#pragma unroll
        for (int j = 0; j < 24; j++) sc[j] = fmaf(ai, sWms[i * 24 + j], sc[j]);
    }

    float scal[16], gate[8];
#pragma unroll
    for (int j = 0; j < 16; j++) { float v = 0.25f * sc[j]; scal[j] = v * sigf(v); }
#pragma unroll
    for (int j = 0; j < 8;  j++) gate[j] = sigf(0.25f * sc[16 + j]);

    float vg[24];
#pragma unroll
    for (int j = 0; j < 8; j++) {
#pragma unroll
        for (int c = 0; c < 3; c++) {
            float acc = 0.f;
#pragma unroll
            for (int i = 0; i < 8; i++) acc = fmaf(a1[i * 3 + c], sWmv[i * 8 + j], acc);
            vg[3 * j + c] = acc * INV_SQRT8 * gate[j];
        }
    }

    float xs[16], xv[24];
    {
        const float4* xn = (const float4*)(g_xnorm + (size_t)n * 40);
#pragma unroll
        for (int q = 0; q < 4; q++) ((float4*)xs)[q] = xn[q];
#pragma unroll
        for (int q = 0; q < 6; q++) ((float4*)xv)[q] = xn[4 + q];
    }

    float xi[40];
    {
        const float4* xp = (const float4*)(x + (size_t)n * 40);
#pragma unroll
        for (int q = 0; q < 10; q++) ((float4*)xi)[q] = xp[q];
    }

    float ob[40];
#pragma unroll
    for (int j = 0; j < 16; j++) {
        float acc = 0.f;
#pragma unroll
        for (int i = 0; i < 16; i++) {
            acc = fmaf(scal[i], sWus[i * 16 + j], acc);
            acc = fmaf(xs[i],   sWss[i * 16 + j], acc);
        }
        ob[j] = xi[j] + rs * 0.25f * acc;
    }
#pragma unroll
    for (int j = 0; j < 8; j++) {
#pragma unroll
        for (int c = 0; c < 3; c++) {
            float acc = 0.f;
#pragma unroll
            for (int i = 0; i < 8; i++) {
                acc = fmaf(vg[3 * i + c], sWuv[i * 8 + j], acc);
                acc = fmaf(xv[3 * i + c], sWsv[i * 8 + j], acc);
            }
            ob[16 + 3 * j + c] = xi[16 + 3 * j + c] + rs * INV_SQRT8 * acc;
        }
    }

    float4* o = (float4*)(out + (size_t)n * 40);
#pragma unroll
    for (int q = 0; q < 10; q++) o[q] = ((float4*)ob)[q];
}

// ---------------------------------------------------------------------------
// Launch
// ---------------------------------------------------------------------------
extern "C" void kernel_launch(void* const* d_in, const int* in_sizes, int n_in,
                              void* d_out, int out_size)
{
    const float* x    = (const float*)d_in[0];
    const int*   esrc = (const int*)  d_in[1];
    const int*   edst = (const int*)  d_in[2];
    const float* esh  = (const float*)d_in[3];
    const float* erbf = (const float*)d_in[4];
    const float* elen = (const float*)d_in[5];
    const float* wr1  = (const float*)d_in[6];
    const float* br1  = (const float*)d_in[7];
    const float* wr2  = (const float*)d_in[8];
    const float* br2  = (const float*)d_in[9];
    const float* wg1  = (const float*)d_in[10];
    const float* bg1  = (const float*)d_in[11];
    const float* wg2  = (const float*)d_in[12];
    const float* bg2  = (const float*)d_in[13];
    const float* Wms  = (const float*)d_in[14];
    const float* Wmv  = (const float*)d_in[15];
    const float* Wus  = (const float*)d_in[16];
    const float* Wuv  = (const float*)d_in[17];
    const float* Wss  = (const float*)d_in[18];
    const float* Wsv  = (const float*)d_in[19];
    const float* rsp  = (const float*)d_in[20];

    int nN = in_sizes[0] / 40;
    int E  = in_sizes[1];
    float* out = (float*)d_out;

    size_t shbytes = (size_t)SMEM_U32 * 4u;   // 225280 B
    cudaFuncSetAttribute(k_edge_mma, cudaFuncAttributeMaxDynamicSharedMemorySize, (int)shbytes);

    k_prep<<<(36864 + 255) / 256, 256>>>(wr2);
    int totalz = nN * 41;
    k_zero<<<(totalz / 4 + 255) / 256, 256>>>(totalz);
    k_norm<<<(nN + 255) / 256, 256>>>(x, nN);
    k_edge_mma<<<(E + 511) / 512, 512, shbytes>>>(esrc, edst, esh, erbf, elen,
                                                  wr1, br1, br2,
                                                  wg1, bg1, wg2, bg2, E, nN);
    k_node<<<(nN + 255) / 256, 256>>>(x, Wms, Wmv, Wus, Wuv, Wss, Wsv, rsp, out, nN);
}

// round 17
// speedup vs baseline: 1.9467x; 1.1089x over previous
#include <cuda_runtime.h>
#include <cuda_bf16.h>
#include <math.h>

typedef unsigned int u32;

// ---------------------------------------------------------------------------
// Problem constants
// ---------------------------------------------------------------------------
#define CUTOFF     5.0f
#define A_PATH     0.20412414523193150818f   // 1/sqrt(24)
#define INV_SQRT3  0.57735026918962576451f
#define INV_SQRT8  0.35355339059327376220f
#define PI_OVER_C  0.62831853071795864769f   // pi / 5

#define NNMAX 50000
__device__ float g_xnorm[NNMAX * 40];
__device__ float g_agg[NNMAX * 41];                      // agg0 | agg1 | norm
__device__ __align__(16) unsigned short g_w2bf[36864];   // W2^T bf16, [j][h] row-major

// smem layout (u32 offsets)
#define OFF_B    0        // 20736 : W2^T bf16 rows of 36 u32 (144 B row stride)
#define OFF_A    20736    // 18432 : A tile, 512 rows of 36 u32
#define OFF_CF   39168    // 12288 : bf16[48][512]  xs(0..15) xv(16..39) bcoef(40..47)
#define OFF_SH   51456    //  2048 : fp32[4][512]   sh0 s1x s1y s1z
#define OFF_EW   53504    //   512 : fp32 ew
#define OFF_DST  54016    //   512 : int dst
#define OFF_BR2  54528    //   576
#define OFF_WR1  55104    //   512
#define OFF_WG1  55616    //   512
#define OFF_WG2  56128    //    64
#define OFF_BR1  56192    //    64
#define OFF_BG1  56256    //    64
#define SMEM_U32 56320    // 225280 bytes

// sigmoid via 1 MUFU: sig(x) = 0.5*tanh(x/2) + 0.5
__device__ __forceinline__ float sigf(float x) {
    float t;
    asm("tanh.approx.f32 %0, %1;" : "=f"(t) : "f"(x * 0.5f));
    return fmaf(0.5f, t, 0.5f);
}

// vector atomic add (sm_90+ baseline PTX)
__device__ __forceinline__ void red2(float* p, float a, float b) {
    asm volatile("red.global.add.v2.f32 [%0], {%1, %2};"
                 :: "l"(p), "f"(a), "f"(b) : "memory");
}

// m16n8k16 bf16 MMA, fp32 accumulate (baseline PTX, works on plain sm_103)
__device__ __forceinline__ void mma_bf16(float& d0, float& d1, float& d2, float& d3,
                                         u32 a0, u32 a1, u32 a2, u32 a3,
                                         u32 b0, u32 b1)
{
    asm volatile(
        "mma.sync.aligned.m16n8k16.row.col.f32.bf16.bf16.f32 "
        "{%0,%1,%2,%3}, {%4,%5,%6,%7}, {%8,%9}, {%0,%1,%2,%3};"
        : "+f"(d0), "+f"(d1), "+f"(d2), "+f"(d3)
        : "r"(a0), "r"(a1), "r"(a2), "r"(a3), "r"(b0), "r"(b1));
}

// ldmatrix x4 (PTX 6.5, sm_75+ baseline)
__device__ __forceinline__ void ldm4(u32& r0, u32& r1, u32& r2, u32& r3, u32 addr)
{
    asm volatile("ldmatrix.sync.aligned.m8n8.x4.shared.b16 {%0,%1,%2,%3}, [%4];"
                 : "=r"(r0), "=r"(r1), "=r"(r2), "=r"(r3) : "r"(addr));
}

__device__ __forceinline__ u32 smem_u32(const void* p) {
    u32 a;
    asm("{ .reg .u64 t; cvta.to.shared.u64 t, %1; cvt.u32.u64 %0, t; }" : "=r"(a) : "l"(p));
    return a;
}

__device__ __forceinline__ u32 pack_bf2(float a, float b) {
    return (u32)__bfloat16_as_ushort(__float2bfloat16_rn(a))
         | ((u32)__bfloat16_as_ushort(__float2bfloat16_rn(b)) << 16);
}
__device__ __forceinline__ float bf2f(__nv_bfloat16 v) { return __bfloat162float(v); }

// ---------------------------------------------------------------------------
// Kernel PRE (fused): [0,nbNorm) irrep-norm | [nbNorm,+nbZero) zero agg |
//                     rest: W2 -> bf16 transpose
// ---------------------------------------------------------------------------
__global__ void __launch_bounds__(256)
k_pre(const float* __restrict__ x, const float* __restrict__ wr2,
      int nN, int nbNorm, int nbZero)
{
    __shared__ float sx[256 * 40];
    int b = blockIdx.x;
    int t = threadIdx.x;

    if (b < nbNorm) {
        int base = b * 256;
        int nNodes = nN - base; if (nNodes > 256) nNodes = 256;
        int nf4 = nNodes * 10;
        const float4* xin = (const float4*)(x + (size_t)base * 40);
        for (int i = t; i < nf4; i += 256) ((float4*)sx)[i] = xin[i];
        __syncthreads();
        if (t < nNodes) {
            float* bb = sx + t * 40;
            float ss = 0.f, vs = 0.f;
#pragma unroll
            for (int i = 0; i < 16; i++) ss = fmaf(bb[i], bb[i], ss);
#pragma unroll
            for (int i = 16; i < 40; i++) vs = fmaf(bb[i], bb[i], vs);
            float inv_s = rsqrtf(ss * 0.0625f + 1e-8f);
            float inv_v = rsqrtf(vs * 0.125f  + 1e-8f);
#pragma unroll
            for (int i = 0; i < 16; i++) bb[i] *= inv_s;
#pragma unroll
            for (int i = 16; i < 40; i++) bb[i] *= inv_v;
        }
        __syncthreads();
        float4* xout = (float4*)(g_xnorm + (size_t)base * 40);
        for (int i = t; i < nf4; i += 256) xout[i] = ((float4*)sx)[i];
    } else if (b < nbNorm + nbZero) {
        int total = nN * 41;
        int i = (b - nbNorm) * 256 + t;
        int nf4 = total >> 2;
        float4 z = make_float4(0.f, 0.f, 0.f, 0.f);
        if (i < nf4) ((float4*)g_agg)[i] = z;
        if (i < (total & 3)) g_agg[(nf4 << 2) + i] = 0.f;
    } else {
        int idx = (b - nbNorm - nbZero) * 256 + t;
        if (idx < 36864) {
            int j = idx >> 6, h = idx & 63;
            g_w2bf[idx] = __bfloat16_as_ushort(__float2bfloat16_rn(wr2[h * 576 + j]));
        }
    }
}

// ---------------------------------------------------------------------------
// Kernel 2: HMMA edge kernel. CTA = 512 edges, 16 warps.
//   ldmatrix fragment loads + paired-tile MMA chains + v2 atomics.
// ---------------------------------------------------------------------------
__global__ void __launch_bounds__(512, 1)
k_edge_mma(const int*   __restrict__ esrc,  const int*   __restrict__ edst,
           const float* __restrict__ esh,   const float* __restrict__ erbf,
           const float* __restrict__ elen,
           const float* __restrict__ wr1,   const float* __restrict__ br1,
           const float* __restrict__ br2g,
           const float* __restrict__ wg1,   const float* __restrict__ bg1,
           const float* __restrict__ wg2,   const float* __restrict__ bg2,
           int E, int nN)
{
    extern __shared__ __align__(16) u32 dynsm[];
    u32*   sB32  = dynsm + OFF_B;
    u32*   sA32  = dynsm + OFF_A;
    __nv_bfloat16* sCF = (__nv_bfloat16*)(dynsm + OFF_CF);
    float* sSh   = (float*)(dynsm + OFF_SH);
    float* sEw   = (float*)(dynsm + OFF_EW);
    int*   sDst  = (int*)(dynsm + OFF_DST);
    float* sBr2  = (float*)(dynsm + OFF_BR2);
    float* sWr1  = (float*)(dynsm + OFF_WR1);
    float* sWg1  = (float*)(dynsm + OFF_WG1);
    float* sWg2  = (float*)(dynsm + OFF_WG2);
    float* sBr1  = (float*)(dynsm + OFF_BR1);
    float* sBg1  = (float*)(dynsm + OFF_BG1);

    const int tid  = threadIdx.x;
    const int lane = tid & 31;
    const int wid  = tid >> 5;
    const int g    = lane >> 2;
    const int tig  = lane & 3;

    // ---- stage B (bf16 W2^T) into padded rows
    {
        const uint4* src = (const uint4*)g_w2bf;
        for (int i = tid; i < 4608; i += 512) {
            int j = i >> 3, q = i & 7;
            *(uint4*)(sB32 + j * 36 + q * 4) = src[i];
        }
    }
    if (tid < 512) { sWr1[tid] = wr1[tid]; sWg1[tid] = wg1[tid]; }
    if (tid < 64)  { sWg2[tid] = wg2[tid]; sBr1[tid] = br1[tid]; sBg1[tid] = bg1[tid]; }
    for (int i = tid; i < 576; i += 512) sBr2[i] = br2g[i];

    // ---- per-edge data loads
    int e = blockIdx.x * 512 + tid;
    bool valid = e < E;
    int ec = valid ? e : (E - 1);
    int src_n = esrc[ec];
    int dst_n = edst[ec];
    float4 sh4 = ((const float4*)esh)[ec];
    const float sh0 = sh4.x, s1x = sh4.y, s1y = sh4.z, s1z = sh4.w;
    float len = elen[ec];

    float rb[8];
    {
        const float4* rp = (const float4*)(erbf + (size_t)ec * 8);
        float4 r0 = rp[0], r1 = rp[1];
        rb[0] = r0.x; rb[1] = r0.y; rb[2] = r0.z; rb[3] = r0.w;
        rb[4] = r1.x; rb[5] = r1.y; rb[6] = r1.z; rb[7] = r1.w;
    }

    __syncthreads();   // weights staged before use

    // ---- chunked hidden MLPs: 8 h-values at a time, stream into A tile
    float z = 0.f;
    {
        u32* arow = sA32 + tid * 36;
#pragma unroll
        for (int c = 0; c < 8; c++) {
            float Hc[8], Gc[8];
#pragma unroll
            for (int k = 0; k < 8; k++) { Hc[k] = sBr1[c*8 + k]; Gc[k] = sBg1[c*8 + k]; }
#pragma unroll
            for (int r = 0; r < 8; r++) {
                float rv = rb[r];
                const float4* wa = (const float4*)(sWr1 + r*64 + c*8);
                const float4* wb = (const float4*)(sWg1 + r*64 + c*8);
                float4 a0 = wa[0], a1 = wa[1];
                float4 b0 = wb[0], b1 = wb[1];
                Hc[0] = fmaf(rv, a0.x, Hc[0]); Hc[1] = fmaf(rv, a0.y, Hc[1]);
                Hc[2] = fmaf(rv, a0.z, Hc[2]); Hc[3] = fmaf(rv, a0.w, Hc[3]);
                Hc[4] = fmaf(rv, a1.x, Hc[4]); Hc[5] = fmaf(rv, a1.y, Hc[5]);
                Hc[6] = fmaf(rv, a1.z, Hc[6]); Hc[7] = fmaf(rv, a1.w, Hc[7]);
                Gc[0] = fmaf(rv, b0.x, Gc[0]); Gc[1] = fmaf(rv, b0.y, Gc[1]);
                Gc[2] = fmaf(rv, b0.z, Gc[2]); Gc[3] = fmaf(rv, b0.w, Gc[3]);
                Gc[4] = fmaf(rv, b1.x, Gc[4]); Gc[5] = fmaf(rv, b1.y, Gc[5]);
                Gc[6] = fmaf(rv, b1.z, Gc[6]); Gc[7] = fmaf(rv, b1.w, Gc[7]);
            }
#pragma unroll
            for (int k = 0; k < 8; k++) { float h = Hc[k]; Hc[k] = h * sigf(h); }
            u32 w0 = pack_bf2(Hc[0], Hc[1]);
            u32 w1 = pack_bf2(Hc[2], Hc[3]);
            u32 w2 = pack_bf2(Hc[4], Hc[5]);
            u32 w3 = pack_bf2(Hc[6], Hc[7]);
            *(uint4*)(arow + c * 4) = make_uint4(w0, w1, w2, w3);
#pragma unroll
            for (int k = 0; k < 8; k++) {
                float gg = Gc[k];
                z = fmaf(gg * sigf(gg), sWg2[c*8 + k], z);
            }
        }
    }
    float gw = sigf(z + bg2[0]);
    float cw = (len < CUTOFF) ? 0.5f * (cosf(PI_OVER_C * len) + 1.0f) : 0.0f;
    float ew = (valid ? cw * gw : 0.0f);

    // ---- per-edge coefficients
    {
        float xe[40];
        const float4* xr = (const float4*)(g_xnorm + (size_t)src_n * 40);
#pragma unroll
        for (int q = 0; q < 10; q++) ((float4*)xe)[q] = xr[q];

#pragma unroll
        for (int i = 0; i < 16; i++) sCF[i * 512 + tid] = __float2bfloat16_rn(xe[i]);             // xs
#pragma unroll
        for (int i = 0; i < 24; i++) sCF[(16 + i) * 512 + tid] = __float2bfloat16_rn(xe[16 + i]); // xv
#pragma unroll
        for (int i = 0; i < 8; i++)                                                               // bcoef
            sCF[(40 + i) * 512 + tid] = __float2bfloat16_rn(
                INV_SQRT3 * (xe[16 + 3*i] * s1x + xe[17 + 3*i] * s1y + xe[18 + 3*i] * s1z));
        sSh[0 * 512 + tid] = sh0;
        sSh[1 * 512 + tid] = s1x;
        sSh[2 * 512 + tid] = s1y;
        sSh[3 * 512 + tid] = s1z;
        sEw[tid] = ew;
        sDst[tid] = valid ? dst_n : 0;
    }
    __syncthreads();

    // ---- warp GEMM + fragment epilogue (rt-serial; paired-tile chains)
    float* agg1 = g_agg + (size_t)nN * 16;
    float* nrmp = g_agg + (size_t)nN * 40;

    // lane-constant ldmatrix address components (bytes)
    const u32 bBase = smem_u32(sB32) + (u32)(lane & 7) * 144u + (u32)(lane >> 3) * 16u;
    const u32 aBase = smem_u32(sA32) + ((u32)((lane >> 3) & 1)) * 1152u
                    + (u32)(lane & 7) * 144u + (u32)(lane >> 4) * 16u;

#pragma unroll 1
    for (int rt = 0; rt < 2; rt++) {
        int e0 = wid * 32 + rt * 16 + g;
        int e1 = e0 + 8;

        float sh0_0 = sSh[e0], sh0_1 = sSh[e1];

        // A fragments for this 16-row tile: 4 ldmatrix.x4
        u32 afr[16];
        {
            u32 aAddr = aBase + (u32)(wid * 32 + rt * 16) * 144u;
#pragma unroll
            for (int ks = 0; ks < 4; ks++)
                ldm4(afr[ks*4+0], afr[ks*4+1], afr[ks*4+2], afr[ks*4+3], aAddr + (u32)ks * 32u);
        }

        float am0a[4] = {0,0,0,0}, am0b[4] = {0,0,0,0};
        float aU0 = 0.f, aU1 = 0.f, bU0 = 0.f, bU1 = 0.f;
        float am1a[6] = {0,0,0,0,0,0}, am1b[6] = {0,0,0,0,0,0};

        // pair of tiles ct, ct+1 -> two interleaved MMA chains
#define TILE_PAIR(CT, DA0,DA1,DA2,DA3, DB0,DB1,DB2,DB3) do {             \
        u32 b0_[8], b1_[8];                                              \
        u32 ad_ = bBase + (u32)(CT) * 1152u;                             \
        ldm4(b0_[0], b0_[1], b0_[2], b0_[3], ad_);                       \
        ldm4(b0_[4], b0_[5], b0_[6], b0_[7], ad_ + 64u);                 \
        ldm4(b1_[0], b1_[1], b1_[2], b1_[3], ad_ + 1152u);               \
        ldm4(b1_[4], b1_[5], b1_[6], b1_[7], ad_ + 1216u);               \
        DA0=0.f; DA1=0.f; DA2=0.f; DA3=0.f;                              \
        DB0=0.f; DB1=0.f; DB2=0.f; DB3=0.f;                              \
        _Pragma("unroll")                                                \
        for (int ks_ = 0; ks_ < 4; ks_++) {                              \
            mma_bf16(DA0,DA1,DA2,DA3,                                    \
                     afr[ks_*4], afr[ks_*4+1], afr[ks_*4+2], afr[ks_*4+3], \
                     b0_[2*ks_], b0_[2*ks_+1]);                          \
            mma_bf16(DB0,DB1,DB2,DB3,                                    \
                     afr[ks_*4], afr[ks_*4+1], afr[ks_*4+2], afr[ks_*4+3], \
                     b1_[2*ks_], b1_[2*ks_+1]);                          \
        }                                                                \
    } while (0)

        // ===== m0 region part 1: i = 0..15, cf = xs_i * sh0; tiles 2i, 2i+1 =====
#pragma unroll 1
        for (int i = 0; i < 16; i++) {
            float cf0 = bf2f(sCF[i * 512 + e0]) * sh0_0;
            float cf1 = bf2f(sCF[i * 512 + e1]) * sh0_1;
            float dA0,dA1,dA2,dA3, dB0,dB1,dB2,dB3;
            TILE_PAIR(2*i, dA0,dA1,dA2,dA3, dB0,dB1,dB2,dB3);
            int J0 = i * 16 + 2 * tig;
            float2 biasA = *(const float2*)(sBr2 + J0);
            float2 biasB = *(const float2*)(sBr2 + J0 + 8);
            am0a[0] = fmaf(cf0, dA0 + biasA.x, am0a[0]);
            am0a[1] = fmaf(cf0, dA1 + biasA.y, am0a[1]);
            am0b[0] = fmaf(cf1, dA2 + biasA.x, am0b[0]);
            am0b[1] = fmaf(cf1, dA3 + biasA.y, am0b[1]);
            am0a[2] = fmaf(cf0, dB0 + biasB.x, am0a[2]);
            am0a[3] = fmaf(cf0, dB1 + biasB.y, am0a[3]);
            am0b[2] = fmaf(cf1, dB2 + biasB.x, am0b[2]);
            am0b[3] = fmaf(cf1, dB3 + biasB.y, am0b[3]);
        }

        // ===== m0 region part 2: i = 16..23, cf = bcoef[i-16]; tiles 2i, 2i+1 =====
#pragma unroll 1
        for (int i = 16; i < 24; i++) {
            float cf0 = bf2f(sCF[(24 + i) * 512 + e0]);   // row 40+(i-16)
            float cf1 = bf2f(sCF[(24 + i) * 512 + e1]);
            float dA0,dA1,dA2,dA3, dB0,dB1,dB2,dB3;
            TILE_PAIR(2*i, dA0,dA1,dA2,dA3, dB0,dB1,dB2,dB3);
            int J0 = i * 16 + 2 * tig;
            float2 biasA = *(const float2*)(sBr2 + J0);
            float2 biasB = *(const float2*)(sBr2 + J0 + 8);
            am0a[0] = fmaf(cf0, dA0 + biasA.x, am0a[0]);
            am0a[1] = fmaf(cf0, dA1 + biasA.y, am0a[1]);
            am0b[0] = fmaf(cf1, dA2 + biasA.x, am0b[0]);
            am0b[1] = fmaf(cf1, dA3 + biasA.y, am0b[1]);
            am0a[2] = fmaf(cf0, dB0 + biasB.x, am0a[2]);
            am0a[3] = fmaf(cf0, dB1 + biasB.y, am0a[3]);
            am0b[2] = fmaf(cf1, dB2 + biasB.x, am0b[2]);
            am0b[3] = fmaf(cf1, dB3 + biasB.y, am0b[3]);
        }

        // ===== w3 region: i = 0..15 step 2, tiles 48+i, 49+i; cf = xs_i =====
#pragma unroll 1
        for (int i = 0; i < 16; i += 2) {
            float xsA0 = bf2f(sCF[i * 512 + e0]);
            float xsA1 = bf2f(sCF[i * 512 + e1]);
            float xsB0 = bf2f(sCF[(i + 1) * 512 + e0]);
            float xsB1 = bf2f(sCF[(i + 1) * 512 + e1]);
            float dA0,dA1,dA2,dA3, dB0,dB1,dB2,dB3;
            TILE_PAIR(48 + i, dA0,dA1,dA2,dA3, dB0,dB1,dB2,dB3);
            int J0 = 384 + i * 8 + 2 * tig;
            float2 biasA = *(const float2*)(sBr2 + J0);
            float2 biasB = *(const float2*)(sBr2 + J0 + 8);
            aU0 = fmaf(xsA0, dA0 + biasA.x, aU0);
            aU1 = fmaf(xsA0, dA1 + biasA.y, aU1);
            bU0 = fmaf(xsA1, dA2 + biasA.x, bU0);
            bU1 = fmaf(xsA1, dA3 + biasA.y, bU1);
            aU0 = fmaf(xsB0, dB0 + biasB.x, aU0);
            aU1 = fmaf(xsB0, dB1 + biasB.y, aU1);
            bU0 = fmaf(xsB1, dB2 + biasB.x, bU0);
            bU1 = fmaf(xsB1, dB3 + biasB.y, bU1);
        }

        // ===== w4 region: i = 0..7 step 2, tiles 64+i, 65+i; pv = xv*sh0 =====
#pragma unroll 1
        for (int i = 0; i < 8; i += 2) {
            float dA0,dA1,dA2,dA3, dB0,dB1,dB2,dB3;
            TILE_PAIR(64 + i, dA0,dA1,dA2,dA3, dB0,dB1,dB2,dB3);
            int J0 = 512 + i * 8 + 2 * tig;
            float2 biasA = *(const float2*)(sBr2 + J0);
            float2 biasB = *(const float2*)(sBr2 + J0 + 8);
            {   // tile 64+i
                float p0x = bf2f(sCF[(16 + 3*i + 0) * 512 + e0]) * sh0_0;
                float p0y = bf2f(sCF[(16 + 3*i + 1) * 512 + e0]) * sh0_0;
                float p0z = bf2f(sCF[(16 + 3*i + 2) * 512 + e0]) * sh0_0;
                float p1x = bf2f(sCF[(16 + 3*i + 0) * 512 + e1]) * sh0_1;
                float p1y = bf2f(sCF[(16 + 3*i + 1) * 512 + e1]) * sh0_1;
                float p1z = bf2f(sCF[(16 + 3*i + 2) * 512 + e1]) * sh0_1;
                float t0 = dA0 + biasA.x, t1 = dA1 + biasA.y;
                float t2 = dA2 + biasA.x, t3 = dA3 + biasA.y;
                am1a[0] = fmaf(p0x, t0, am1a[0]);
                am1a[1] = fmaf(p0y, t0, am1a[1]);
                am1a[2] = fmaf(p0z, t0, am1a[2]);
                am1a[3] = fmaf(p0x, t1, am1a[3]);
                am1a[4] = fmaf(p0y, t1, am1a[4]);
                am1a[5] = fmaf(p0z, t1, am1a[5]);
                am1b[0] = fmaf(p1x, t2, am1b[0]);
                am1b[1] = fmaf(p1y, t2, am1b[1]);
                am1b[2] = fmaf(p1z, t2, am1b[2]);
                am1b[3] = fmaf(p1x, t3, am1b[3]);
                am1b[4] = fmaf(p1y, t3, am1b[4]);
                am1b[5] = fmaf(p1z, t3, am1b[5]);
            }
            {   // tile 65+i
                int ii = i + 1;
                float p0x = bf2f(sCF[(16 + 3*ii + 0) * 512 + e0]) * sh0_0;
                float p0y = bf2f(sCF[(16 + 3*ii + 1) * 512 + e0]) * sh0_0;
                float p0z = bf2f(sCF[(16 + 3*ii + 2) * 512 + e0]) * sh0_0;
                float p1x = bf2f(sCF[(16 + 3*ii + 0) * 512 + e1]) * sh0_1;
                float p1y = bf2f(sCF[(16 + 3*ii + 1) * 512 + e1]) * sh0_1;
                float p1z = bf2f(sCF[(16 + 3*ii + 2) * 512 + e1]) * sh0_1;
                float t0 = dB0 + biasB.x, t1 = dB1 + biasB.y;
                float t2 = dB2 + biasB.x, t3 = dB3 + biasB.y;
                am1a[0] = fmaf(p0x, t0, am1a[0]);
                am1a[1] = fmaf(p0y, t0, am1a[1]);
                am1a[2] = fmaf(p0z, t0, am1a[2]);
                am1a[3] = fmaf(p0x, t1, am1a[3]);
                am1a[4] = fmaf(p0y, t1, am1a[4]);
                am1a[5] = fmaf(p0z, t1, am1a[5]);
                am1b[0] = fmaf(p1x, t2, am1b[0]);
                am1b[1] = fmaf(p1y, t2, am1b[1]);
                am1b[2] = fmaf(p1z, t2, am1b[2]);
                am1b[3] = fmaf(p1x, t3, am1b[3]);
                am1b[4] = fmaf(p1y, t3, am1b[4]);
                am1b[5] = fmaf(p1z, t3, am1b[5]);
            }
        }
#undef TILE_PAIR

        // fold U (w3 path) into m1 with each edge's sh1
        {
            float sx = sSh[512 + e0], sy = sSh[1024 + e0], sz = sSh[1536 + e0];
            am1a[0] = fmaf(aU0, sx, am1a[0]);
            am1a[1] = fmaf(aU0, sy, am1a[1]);
            am1a[2] = fmaf(aU0, sz, am1a[2]);
            am1a[3] = fmaf(aU1, sx, am1a[3]);
            am1a[4] = fmaf(aU1, sy, am1a[4]);
            am1a[5] = fmaf(aU1, sz, am1a[5]);
            sx = sSh[512 + e1]; sy = sSh[1024 + e1]; sz = sSh[1536 + e1];
            am1b[0] = fmaf(bU0, sx, am1b[0]);
            am1b[1] = fmaf(bU0, sy, am1b[1]);
            am1b[2] = fmaf(bU0, sz, am1b[2]);
            am1b[3] = fmaf(bU1, sx, am1b[3]);
            am1b[4] = fmaf(bU1, sy, am1b[4]);
            am1b[5] = fmaf(bU1, sz, am1b[5]);
        }

        // ---- scatter: v2 vector atomics (lane-local, 8B-aligned slots)
        {
            float ew0 = sEw[e0];
            float ew1 = sEw[e1];
            int   dA  = sDst[e0];
            int   dB  = sDst[e1];
            float ca = A_PATH * ew0;
            float cb = A_PATH * ew1;
            int j0 = 2 * tig;

            float* base0 = g_agg + (size_t)dA * 16;
            red2(base0 + j0,     ca * am0a[0], ca * am0a[1]);
            red2(base0 + j0 + 8, ca * am0a[2], ca * am0a[3]);
            float* base1 = g_agg + (size_t)dB * 16;
            red2(base1 + j0,     cb * am0b[0], cb * am0b[1]);
            red2(base1 + j0 + 8, cb * am0b[2], cb * am0b[3]);

            float* v0 = agg1 + (size_t)dA * 24 + 3 * j0;
            red2(v0 + 0, ca * am1a[0], ca * am1a[1]);
            red2(v0 + 2, ca * am1a[2], ca * am1a[3]);
            red2(v0 + 4, ca * am1a[4], ca * am1a[5]);
            float* v1 = agg1 + (size_t)dB * 24 + 3 * j0;
            red2(v1 + 0, cb * am1b[0], cb * am1b[1]);
            red2(v1 + 2, cb * am1b[2], cb * am1b[3]);
            red2(v1 + 4, cb * am1b[4], cb * am1b[5]);

            if (tig == 0) {
                atomicAdd(nrmp + dA, ew0);
                atomicAdd(nrmp + dB, ew1);
            }
        }
    }
}

// ---------------------------------------------------------------------------
// Kernel 3: node update (gates + small matmuls + residual)
// ---------------------------------------------------------------------------
__global__ void __launch_bounds__(256)
k_node(const float* __restrict__ x,
       const float* __restrict__ Wms, const float* __restrict__ Wmv,
       const float* __restrict__ Wus, const float* __restrict__ Wuv,
       const float* __restrict__ Wss, const float* __restrict__ Wsv,
       const float* __restrict__ rsp,
       float* __restrict__ out, int nN)
{
    __shared__ float sWms[384], sWmv[64], sWus[256], sWuv[64], sWss[256], sWsv[64];
    int t = threadIdx.x;
    for (int i = t; i < 384; i += blockDim.x) sWms[i] = Wms[i];
    for (int i = t; i < 256; i += blockDim.x) { sWus[i] = Wus[i]; sWss[i] = Wss[i]; }
    for (int i = t; i < 64;  i += blockDim.x) { sWmv[i] = Wmv[i]; sWuv[i] = Wuv[i]; sWsv[i] = Wsv[i]; }
    __syncthreads();

    int n = blockIdx.x * blockDim.x + t;
    if (n >= nN) return;

    float rs = rsp[0];
    float nrm = fmaxf(g_agg[(size_t)nN * 40 + n], 1e-8f);
    float inv = __fdividef(1.0f, nrm);

    float a0[16], a1[24];
    {
        const float4* p0 = (const float4*)(g_agg + (size_t)n * 16);
#pragma unroll
        for (int q = 0; q < 4; q++) ((float4*)a0)[q] = p0[q];
        const float4* p1 = (const float4*)(g_agg + (size_t)nN * 16 + (size_t)n * 24);
#pragma unroll
        for (int q = 0; q < 6; q++) ((float4*)a1)[q] = p1[q];
    }
#pragma unroll
    for (int j = 0; j < 16; j++) a0[j] *= inv;
#pragma unroll
    for (int j = 0; j < 24; j++) a1[j] *= inv;

    float sc[24];
#pragma unroll
    for (int j = 0; j < 24; j++) sc[j] = 0.f;
#pragma unroll
    for (int i = 0; i < 16; i++) {
        float ai = a0[i];
#pragma unroll
        for (int j = 0; j < 24; j++) sc[j] = fmaf(ai, sWms[i * 24 + j], sc[j]);
    }

    float scal[16], gate[8];
#pragma unroll
    for (int j = 0; j < 16; j++) { float v = 0.25f * sc[j]; scal[j] = v * sigf(v); }
#pragma unroll
    for (int j = 0; j < 8;  j++) gate[j] = sigf(0.25f * sc[16 + j]);

    float vg[24];
#pragma unroll
    for (int j = 0; j < 8; j++) {
#pragma unroll
        for (int c = 0; c < 3; c++) {
            float acc = 0.f;
#pragma unroll
            for (int i = 0; i < 8; i++) acc = fmaf(a1[i * 3 + c], sWmv[i * 8 + j], acc);
            vg[3 * j + c] = acc * INV_SQRT8 * gate[j];
        }
    }

    float xs[16], xv[24];
    {
        const float4* xn = (const float4*)(g_xnorm + (size_t)n * 40);
#pragma unroll
        for (int q = 0; q < 4; q++) ((float4*)xs)[q] = xn[q];
#pragma unroll
        for (int q = 0; q < 6; q++) ((float4*)xv)[q] = xn[4 + q];
    }

    float xi[40];
    {
        const float4* xp = (const float4*)(x + (size_t)n * 40);
#pragma unroll
        for (int q = 0; q < 10; q++) ((float4*)xi)[q] = xp[q];
    }

    float ob[40];
#pragma unroll
    for (int j = 0; j < 16; j++) {
        float acc = 0.f;
#pragma unroll
        for (int i = 0; i < 16; i++) {
            acc = fmaf(scal[i], sWus[i * 16 + j], acc);
            acc = fmaf(xs[i],   sWss[i * 16 + j], acc);
        }
        ob[j] = xi[j] + rs * 0.25f * acc;
    }
#pragma unroll
    for (int j = 0; j < 8; j++) {
#pragma unroll
        for (int c = 0; c < 3; c++) {
            float acc = 0.f;
#pragma unroll
            for (int i = 0; i < 8; i++) {
                acc = fmaf(vg[3 * i + c], sWuv[i * 8 + j], acc);
                acc = fmaf(xv[3 * i + c], sWsv[i * 8 + j], acc);
            }
            ob[16 + 3 * j + c] = xi[16 + 3 * j + c] + rs * INV_SQRT8 * acc;
        }
    }

    float4* o = (float4*)(out + (size_t)n * 40);
#pragma unroll
    for (int q = 0; q < 10; q++) o[q] = ((float4*)ob)[q];
}

// ---------------------------------------------------------------------------
// Launch
// ---------------------------------------------------------------------------
extern "C" void kernel_launch(void* const* d_in, const int* in_sizes, int n_in,
                              void* d_out, int out_size)
{
    const float* x    = (const float*)d_in[0];
    const int*   esrc = (const int*)  d_in[1];
    const int*   edst = (const int*)  d_in[2];
    const float* esh  = (const float*)d_in[3];
    const float* erbf = (const float*)d_in[4];
    const float* elen = (const float*)d_in[5];
    const float* wr1  = (const float*)d_in[6];
    const float* br1  = (const float*)d_in[7];
    const float* wr2  = (const float*)d_in[8];
    const float* br2  = (const float*)d_in[9];
    const float* wg1  = (const float*)d_in[10];
    const float* bg1  = (const float*)d_in[11];
    const float* wg2  = (const float*)d_in[12];
    const float* bg2  = (const float*)d_in[13];
    const float* Wms  = (const float*)d_in[14];
    const float* Wmv  = (const float*)d_in[15];
    const float* Wus  = (const float*)d_in[16];
    const float* Wuv  = (const float*)d_in[17];
    const float* Wss  = (const float*)d_in[18];
    const float* Wsv  = (const float*)d_in[19];
    const float* rsp  = (const float*)d_in[20];

    int nN = in_sizes[0] / 40;
    int E  = in_sizes[1];
    float* out = (float*)d_out;

    size_t shbytes = (size_t)SMEM_U32 * 4u;   // 225280 B
    cudaFuncSetAttribute(k_edge_mma, cudaFuncAttributeMaxDynamicSharedMemorySize, (int)shbytes);

    int nbNorm = (nN + 255) / 256;
    int nbZero = ((nN * 41) / 4 + 255) / 256;
    int nbPrep = (36864 + 255) / 256;
    k_pre<<<nbNorm + nbZero + nbPrep, 256>>>(x, wr2, nN, nbNorm, nbZero);
    k_edge_mma<<<(E + 511) / 512, 512, shbytes>>>(esrc, edst, esh, erbf, elen,
                                                  wr1, br1, br2,
                                                  wg1, bg1, wg2, bg2, E, nN);
    k_node<<<(nN + 255) / 256, 256>>>(x, Wms, Wmv, Wus, Wuv, Wss, Wsv, rsp, out, nN);
}